// round 3
// baseline (speedup 1.0000x reference)
#include <cuda_runtime.h>

#define D_MODEL 1024
#define NH      16
#define HDIM    64
#define B_      8
#define TQ      1024
#define NKV     1536
#define SCALE   0.125f   // HD^-0.5 = 64^-0.5

#define LDP 68           // padded smem row stride (floats); 68*4B = 272B = 17*16B (float4-aligned)

// Scratch (allocation-free rule: __device__ globals)
__device__ float g_q[B_ * TQ * D_MODEL];     // Q projection  [B*T, D]
__device__ float g_k[B_ * NKV * D_MODEL];    // K projection  [B*N, D]
__device__ float g_v[B_ * NKV * D_MODEL];    // V projection  [B*N, D]
__device__ float g_ctx[B_ * TQ * D_MODEL];   // attention out [B*T, D]

// ---------------------------------------------------------------------------
// C[m,n] = sum_k A[m,k] * W[n,k] + bias[n]   (torch Linear: x @ W.T + b)
// Tiles: BM=BN=128, BK=16, 256 threads, 8x8 per-thread microtile.
// M % 128 == 0, N % 128 == 0, K % 16 == 0 for all our shapes (no bounds checks).
// ---------------------------------------------------------------------------
__global__ __launch_bounds__(256) void sgemm_nt_bias(
    const float* __restrict__ A, const float* __restrict__ W,
    const float* __restrict__ bias, float* __restrict__ C,
    int M, int N, int K)
{
    __shared__ float As[16][128];
    __shared__ float Bs[16][128];
    const int tid = threadIdx.x;
    const int tx = tid & 15;        // 0..15 -> n direction
    const int ty = tid >> 4;        // 0..15 -> m direction
    const int bm = blockIdx.y * 128;
    const int bn = blockIdx.x * 128;

    float acc[8][8];
#pragma unroll
    for (int i = 0; i < 8; i++)
#pragma unroll
        for (int j = 0; j < 8; j++) acc[i][j] = 0.f;

    for (int k0 = 0; k0 < K; k0 += 16) {
        // load 128x16 tiles of A and W (transpose-on-store); 2 float4 each
#pragma unroll
        for (int u = 0; u < 2; u++) {
            int idx = tid + u * 256;          // 0..511
            int row = idx >> 2;               // 0..127
            int kq  = (idx & 3) * 4;          // 0,4,8,12
            float4 va = *(const float4*)(A + (size_t)(bm + row) * K + k0 + kq);
            As[kq + 0][row] = va.x; As[kq + 1][row] = va.y;
            As[kq + 2][row] = va.z; As[kq + 3][row] = va.w;
            float4 vb = *(const float4*)(W + (size_t)(bn + row) * K + k0 + kq);
            Bs[kq + 0][row] = vb.x; Bs[kq + 1][row] = vb.y;
            Bs[kq + 2][row] = vb.z; Bs[kq + 3][row] = vb.w;
        }
        __syncthreads();
#pragma unroll
        for (int kk = 0; kk < 16; kk++) {
            float a[8], b[8];
            *(float4*)&a[0] = *(const float4*)&As[kk][ty * 8];
            *(float4*)&a[4] = *(const float4*)&As[kk][ty * 8 + 4];
            *(float4*)&b[0] = *(const float4*)&Bs[kk][tx * 8];
            *(float4*)&b[4] = *(const float4*)&Bs[kk][tx * 8 + 4];
#pragma unroll
            for (int i = 0; i < 8; i++)
#pragma unroll
                for (int j = 0; j < 8; j++)
                    acc[i][j] += a[i] * b[j];
        }
        __syncthreads();
    }

#pragma unroll
    for (int i = 0; i < 8; i++) {
        int row = bm + ty * 8 + i;
#pragma unroll
        for (int j0 = 0; j0 < 8; j0 += 4) {
            int col = bn + tx * 8 + j0;
            float4 r;
            r.x = acc[i][j0 + 0] + bias[col + 0];
            r.y = acc[i][j0 + 1] + bias[col + 1];
            r.z = acc[i][j0 + 2] + bias[col + 2];
            r.w = acc[i][j0 + 3] + bias[col + 3];
            *(float4*)(C + (size_t)row * N + col) = r;
        }
    }
}

// ---------------------------------------------------------------------------
// Flash-attention: grid (T/64, B*H). Block: 256 threads as 16x16, 4x4 per
// thread. Q tile 64x64 (smem, d-major), loop over 24 KV tiles of 64 rows.
// Online softmax; P staged through smem reusing the K buffer.
// ---------------------------------------------------------------------------
__global__ __launch_bounds__(256) void attn_kernel(
    const float* __restrict__ qb, const float* __restrict__ kb,
    const float* __restrict__ vb, const unsigned char* __restrict__ mask,
    float* __restrict__ ctx)
{
    extern __shared__ float sm[];
    float* Qs = sm;                 // [64 d][LDP] : Qs[d*LDP + r]  (pre-scaled)
    float* Ks = Qs + 64 * LDP;      // [64 d][LDP] : Ks[d*LDP + c]; reused as Ps[n*LDP + r]
    float* Vs = Ks + 64 * LDP;      // [64 n][LDP] : Vs[n*LDP + d]  (natural)

    const int tid = threadIdx.x;
    const int tx = tid & 15;        // column group (n or d-out)
    const int ty = tid >> 4;        // row group (q rows)
    const int qt = blockIdx.x;      // q tile
    const int bh = blockIdx.y;
    const int b  = bh / NH;
    const int h  = bh % NH;
    const int t0 = qt * 64;

    // ---- load Q tile transposed (once), pre-multiplied by softmax scale ----
    const float* qbase = qb + ((size_t)b * TQ + t0) * D_MODEL + h * HDIM;
#pragma unroll
    for (int u = 0; u < 4; u++) {
        int idx = tid + u * 256;        // 0..1023
        int r   = idx >> 4;             // 0..63
        int dq  = (idx & 15) * 4;       // 0..60
        float4 v = *(const float4*)(qbase + (size_t)r * D_MODEL + dq);
        Qs[(dq + 0) * LDP + r] = v.x * SCALE;
        Qs[(dq + 1) * LDP + r] = v.y * SCALE;
        Qs[(dq + 2) * LDP + r] = v.z * SCALE;
        Qs[(dq + 3) * LDP + r] = v.w * SCALE;
    }

    float m_run[4], l_run[4], acc[4][4];
#pragma unroll
    for (int i = 0; i < 4; i++) {
        m_run[i] = -1e30f; l_run[i] = 0.f;
#pragma unroll
        for (int j = 0; j < 4; j++) acc[i][j] = 0.f;
    }

    for (int n0 = 0; n0 < NKV; n0 += 64) {
        // ---- load K (transposed) and V (natural) tiles ----
        const float* kbase = kb + ((size_t)b * NKV + n0) * D_MODEL + h * HDIM;
        const float* vbase = vb + ((size_t)b * NKV + n0) * D_MODEL + h * HDIM;
#pragma unroll
        for (int u = 0; u < 4; u++) {
            int idx = tid + u * 256;
            int r   = idx >> 4;
            int dq  = (idx & 15) * 4;
            float4 kv4 = *(const float4*)(kbase + (size_t)r * D_MODEL + dq);
            Ks[(dq + 0) * LDP + r] = kv4.x;
            Ks[(dq + 1) * LDP + r] = kv4.y;
            Ks[(dq + 2) * LDP + r] = kv4.z;
            Ks[(dq + 3) * LDP + r] = kv4.w;
            float4 vv4 = *(const float4*)(vbase + (size_t)r * D_MODEL + dq);
            *(float4*)&Vs[r * LDP + dq] = vv4;
        }
        __syncthreads();

        // ---- S = (Q*scale) @ K^T for this tile: 4x4 per thread ----
        float s[4][4];
#pragma unroll
        for (int i = 0; i < 4; i++)
#pragma unroll
            for (int j = 0; j < 4; j++) s[i][j] = 0.f;
#pragma unroll 16
        for (int d = 0; d < 64; d++) {
            float4 a = *(const float4*)&Qs[d * LDP + ty * 4];
            float4 k4 = *(const float4*)&Ks[d * LDP + tx * 4];
            float av[4] = {a.x, a.y, a.z, a.w};
            float bv4[4] = {k4.x, k4.y, k4.z, k4.w};
#pragma unroll
            for (int i = 0; i < 4; i++)
#pragma unroll
                for (int j = 0; j < 4; j++)
                    s[i][j] += av[i] * bv4[j];
        }

        // ---- key padding mask ----
        const unsigned char* mrow = mask + (size_t)b * NKV + n0 + tx * 4;
#pragma unroll
        for (int j = 0; j < 4; j++) {
            if (mrow[j]) {
#pragma unroll
                for (int i = 0; i < 4; i++) s[i][j] = -1e30f;
            }
        }

        // ---- online softmax (row reductions across the 16 tx lanes) ----
        float corr[4];
#pragma unroll
        for (int i = 0; i < 4; i++) {
            float rm = fmaxf(fmaxf(s[i][0], s[i][1]), fmaxf(s[i][2], s[i][3]));
            rm = fmaxf(rm, __shfl_xor_sync(0xffffffffu, rm, 1));
            rm = fmaxf(rm, __shfl_xor_sync(0xffffffffu, rm, 2));
            rm = fmaxf(rm, __shfl_xor_sync(0xffffffffu, rm, 4));
            rm = fmaxf(rm, __shfl_xor_sync(0xffffffffu, rm, 8));
            float mn = fmaxf(m_run[i], rm);
            corr[i] = __expf(m_run[i] - mn);
            m_run[i] = mn;
            float rs = 0.f;
#pragma unroll
            for (int j = 0; j < 4; j++) {
                float p = __expf(s[i][j] - mn);
                s[i][j] = p;
                rs += p;
            }
            rs += __shfl_xor_sync(0xffffffffu, rs, 1);
            rs += __shfl_xor_sync(0xffffffffu, rs, 2);
            rs += __shfl_xor_sync(0xffffffffu, rs, 4);
            rs += __shfl_xor_sync(0xffffffffu, rs, 8);
            l_run[i] = l_run[i] * corr[i] + rs;
        }

        __syncthreads();             // all S reads of Ks done before overwrite
        // ---- stage P into (reused) K buffer: Ps[n][r] ----
        float* Ps = Ks;
#pragma unroll
        for (int j = 0; j < 4; j++) {
            float4 pv = make_float4(s[0][j], s[1][j], s[2][j], s[3][j]);
            *(float4*)&Ps[(tx * 4 + j) * LDP + ty * 4] = pv;
        }
        __syncthreads();

        // ---- O = O*corr + P @ V ----
#pragma unroll
        for (int i = 0; i < 4; i++)
#pragma unroll
            for (int j = 0; j < 4; j++) acc[i][j] *= corr[i];
#pragma unroll 16
        for (int n = 0; n < 64; n++) {
            float4 p  = *(const float4*)&Ps[n * LDP + ty * 4];
            float4 vv = *(const float4*)&Vs[n * LDP + tx * 4];
            float pv[4] = {p.x, p.y, p.z, p.w};
            float vvv[4] = {vv.x, vv.y, vv.z, vv.w};
#pragma unroll
            for (int i = 0; i < 4; i++)
#pragma unroll
                for (int j = 0; j < 4; j++)
                    acc[i][j] += pv[i] * vvv[j];
        }
        __syncthreads();             // before next tile overwrites Ks/Vs
    }

    // ---- normalize and write ctx ----
    float* obase = ctx + ((size_t)b * TQ + t0) * D_MODEL + h * HDIM;
#pragma unroll
    for (int i = 0; i < 4; i++) {
        float inv = 1.f / l_run[i];
        float4 r;
        r.x = acc[i][0] * inv;
        r.y = acc[i][1] * inv;
        r.z = acc[i][2] * inv;
        r.w = acc[i][3] * inv;
        *(float4*)(obase + (size_t)(ty * 4 + i) * D_MODEL + tx * 4) = r;
    }
}

// ---------------------------------------------------------------------------
extern "C" void kernel_launch(void* const* d_in, const int* in_sizes, int n_in,
                              void* d_out, int out_size)
{
    const float* query = (const float*)d_in[0];
    const float* kv    = (const float*)d_in[1];
    const unsigned char* mask = (const unsigned char*)d_in[2];
    const float* Wq = (const float*)d_in[3];
    const float* bq = (const float*)d_in[4];
    const float* Wk = (const float*)d_in[5];
    const float* bk = (const float*)d_in[6];
    const float* Wv = (const float*)d_in[7];
    const float* bv = (const float*)d_in[8];
    const float* Wo = (const float*)d_in[9];
    const float* bo = (const float*)d_in[10];
    float* out = (float*)d_out;

    // One-time host-side setup (no device work, no capture nodes).
    static float *qb = nullptr, *kb = nullptr, *vbuf = nullptr, *cb = nullptr;
    static const int SMEM_ATTN = 3 * 64 * LDP * 4;   // 52224 bytes
    if (!qb) {
        cudaGetSymbolAddress((void**)&qb,   g_q);
        cudaGetSymbolAddress((void**)&kb,   g_k);
        cudaGetSymbolAddress((void**)&vbuf, g_v);
        cudaGetSymbolAddress((void**)&cb,   g_ctx);
        cudaFuncSetAttribute(attn_kernel,
                             cudaFuncAttributeMaxDynamicSharedMemorySize, SMEM_ATTN);
    }

    dim3 blk(256);
    // Projections: C = A @ W^T + b
    sgemm_nt_bias<<<dim3(8, 64), blk>>>(query, Wq, bq, qb,  B_ * TQ,  D_MODEL, D_MODEL);
    sgemm_nt_bias<<<dim3(8, 96), blk>>>(kv,    Wk, bk, kb,  B_ * NKV, D_MODEL, D_MODEL);
    sgemm_nt_bias<<<dim3(8, 96), blk>>>(kv,    Wv, bv, vbuf,B_ * NKV, D_MODEL, D_MODEL);

    // Attention
    attn_kernel<<<dim3(TQ / 64, B_ * NH), blk, SMEM_ATTN>>>(qb, kb, vbuf, mask, cb);

    // Output projection
    sgemm_nt_bias<<<dim3(8, 64), blk>>>(cb, Wo, bo, out, B_ * TQ, D_MODEL, D_MODEL);
}

// round 6
// speedup vs baseline: 1.6154x; 1.6154x over previous
#include <cuda_runtime.h>
#include <cstdint>

#define D_MODEL 1024
#define NH      16
#define HDIM    64
#define B_      8
#define TQ      1024
#define NKV     1536
#define SCALE   0.125f   // HD^-0.5 = 64^-0.5

#define LDP 68           // attn smem row stride (floats)

// Scratch (allocation-free rule: __device__ globals)
__device__ float g_q[B_ * TQ * D_MODEL];     // Q projection  [B*T, D]
__device__ float g_k[B_ * NKV * D_MODEL];    // K projection  [B*N, D]
__device__ float g_v[B_ * NKV * D_MODEL];    // V projection  [B*N, D]
__device__ float g_ctx[B_ * TQ * D_MODEL];   // attention out [B*T, D]

// ---------------------------------------------------------------------------
// tf32 helpers
// ---------------------------------------------------------------------------
__device__ __forceinline__ float to_tf32(float x) {
    uint32_t y;                                   // cvt to tf32 needs .b32 dst
    asm("cvt.rna.tf32.f32 %0, %1;" : "=r"(y) : "f"(x));
    return __uint_as_float(y);
}

__device__ __forceinline__ void mma_tf32_16x8x8(
    float& c0, float& c1, float& c2, float& c3,
    uint32_t a0, uint32_t a1, uint32_t a2, uint32_t a3,
    uint32_t b0, uint32_t b1)
{
    asm volatile(
        "mma.sync.aligned.m16n8k8.row.col.f32.tf32.tf32.f32 "
        "{%0,%1,%2,%3}, {%4,%5,%6,%7}, {%8,%9}, {%0,%1,%2,%3};\n"
        : "+f"(c0), "+f"(c1), "+f"(c2), "+f"(c3)
        : "r"(a0), "r"(a1), "r"(a2), "r"(a3), "r"(b0), "r"(b1));
}

// ---------------------------------------------------------------------------
// C[m,n] = sum_k A[m,k] * W[n,k] + bias[n]   (x @ W.T + b), tf32 tensor cores.
// BM=BN=128, BK=32. 256 threads = 8 warps; warp tile 64x32 (4x4 m16n8k8 frags).
// M%128==0, N%128==0, K%32==0 (true for all our shapes).
// ---------------------------------------------------------------------------
__global__ __launch_bounds__(256) void gemm_tf32_nt_bias(
    const float* __restrict__ A, const float* __restrict__ W,
    const float* __restrict__ bias, float* __restrict__ C,
    int M, int N, int K)
{
    __shared__ float As[128][36];
    __shared__ float Bs[128][36];

    const int tid  = threadIdx.x;
    const int wid  = tid >> 5;
    const int lane = tid & 31;
    const int g    = lane >> 2;      // 0..7
    const int tig  = lane & 3;       // 0..3
    const int warp_m = (wid >> 2) * 64;   // 0,64
    const int warp_n = (wid & 3) * 32;    // 0,32,64,96
    const int bm = blockIdx.y * 128;
    const int bn = blockIdx.x * 128;

    // global load mapping: 32 rows x 8 float4 per pass, 4 passes
    const int lrow = tid >> 3;        // 0..31
    const int lcol = (tid & 7) * 4;   // 0..28

    float acc[4][4][4];
#pragma unroll
    for (int mf = 0; mf < 4; mf++)
#pragma unroll
        for (int nf = 0; nf < 4; nf++)
#pragma unroll
            for (int r = 0; r < 4; r++) acc[mf][nf][r] = 0.f;

    const float* aptr = A + (size_t)(bm + lrow) * K + lcol;
    const float* bptr = W + (size_t)(bn + lrow) * K + lcol;

    float4 ra[4], rb[4];
    // prologue: load tile 0
#pragma unroll
    for (int u = 0; u < 4; u++) {
        ra[u] = *(const float4*)(aptr + (size_t)u * 32 * K);
        rb[u] = *(const float4*)(bptr + (size_t)u * 32 * K);
    }
#pragma unroll
    for (int u = 0; u < 4; u++) {
        int r = lrow + u * 32;
        As[r][lcol + 0] = to_tf32(ra[u].x); As[r][lcol + 1] = to_tf32(ra[u].y);
        As[r][lcol + 2] = to_tf32(ra[u].z); As[r][lcol + 3] = to_tf32(ra[u].w);
        Bs[r][lcol + 0] = to_tf32(rb[u].x); Bs[r][lcol + 1] = to_tf32(rb[u].y);
        Bs[r][lcol + 2] = to_tf32(rb[u].z); Bs[r][lcol + 3] = to_tf32(rb[u].w);
    }
    __syncthreads();

    const int kTiles = K >> 5;
    for (int kt = 0; kt < kTiles; kt++) {
        const bool notlast = (kt + 1 < kTiles);
        if (notlast) {
            const float* ap = aptr + (size_t)(kt + 1) * 32;
            const float* bp = bptr + (size_t)(kt + 1) * 32;
#pragma unroll
            for (int u = 0; u < 4; u++) {
                ra[u] = *(const float4*)(ap + (size_t)u * 32 * K);
                rb[u] = *(const float4*)(bp + (size_t)u * 32 * K);
            }
        }

        // compute: 4 k8-steps
#pragma unroll
        for (int ks = 0; ks < 4; ks++) {
            const int k0 = ks * 8;
            uint32_t af[4][4];
#pragma unroll
            for (int mf = 0; mf < 4; mf++) {
                int row = warp_m + mf * 16;
                af[mf][0] = __float_as_uint(As[row + g    ][k0 + tig    ]);
                af[mf][1] = __float_as_uint(As[row + g + 8][k0 + tig    ]);
                af[mf][2] = __float_as_uint(As[row + g    ][k0 + tig + 4]);
                af[mf][3] = __float_as_uint(As[row + g + 8][k0 + tig + 4]);
            }
            uint32_t bf[4][2];
#pragma unroll
            for (int nf = 0; nf < 4; nf++) {
                int col = warp_n + nf * 8;
                bf[nf][0] = __float_as_uint(Bs[col + g][k0 + tig    ]);
                bf[nf][1] = __float_as_uint(Bs[col + g][k0 + tig + 4]);
            }
#pragma unroll
            for (int mf = 0; mf < 4; mf++)
#pragma unroll
                for (int nf = 0; nf < 4; nf++)
                    mma_tf32_16x8x8(acc[mf][nf][0], acc[mf][nf][1],
                                    acc[mf][nf][2], acc[mf][nf][3],
                                    af[mf][0], af[mf][1], af[mf][2], af[mf][3],
                                    bf[nf][0], bf[nf][1]);
        }
        __syncthreads();
        if (notlast) {
#pragma unroll
            for (int u = 0; u < 4; u++) {
                int r = lrow + u * 32;
                As[r][lcol + 0] = to_tf32(ra[u].x); As[r][lcol + 1] = to_tf32(ra[u].y);
                As[r][lcol + 2] = to_tf32(ra[u].z); As[r][lcol + 3] = to_tf32(ra[u].w);
                Bs[r][lcol + 0] = to_tf32(rb[u].x); Bs[r][lcol + 1] = to_tf32(rb[u].y);
                Bs[r][lcol + 2] = to_tf32(rb[u].z); Bs[r][lcol + 3] = to_tf32(rb[u].w);
            }
            __syncthreads();
        }
    }

    // epilogue: c0,c1 @ (g, 2tig), c2,c3 @ (g+8, 2tig)
#pragma unroll
    for (int mf = 0; mf < 4; mf++) {
        int row0 = bm + warp_m + mf * 16 + g;
#pragma unroll
        for (int nf = 0; nf < 4; nf++) {
            int col = bn + warp_n + nf * 8 + 2 * tig;
            float bv0 = bias[col], bv1 = bias[col + 1];
            *(float2*)&C[(size_t)row0 * N + col] =
                make_float2(acc[mf][nf][0] + bv0, acc[mf][nf][1] + bv1);
            *(float2*)&C[(size_t)(row0 + 8) * N + col] =
                make_float2(acc[mf][nf][2] + bv0, acc[mf][nf][3] + bv1);
        }
    }
}

// ---------------------------------------------------------------------------
// Flash-attention (unchanged R3 baseline): grid (T/64, B*H), 256 threads as
// 16x16, 4x4 per thread, online softmax, P staged through reused K buffer.
// ---------------------------------------------------------------------------
__global__ __launch_bounds__(256) void attn_kernel(
    const float* __restrict__ qb, const float* __restrict__ kb,
    const float* __restrict__ vb, const unsigned char* __restrict__ mask,
    float* __restrict__ ctx)
{
    extern __shared__ float sm[];
    float* Qs = sm;                 // [64 d][LDP]
    float* Ks = Qs + 64 * LDP;      // [64 d][LDP]; reused as Ps[n*LDP + r]
    float* Vs = Ks + 64 * LDP;      // [64 n][LDP]

    const int tid = threadIdx.x;
    const int tx = tid & 15;
    const int ty = tid >> 4;
    const int qt = blockIdx.x;
    const int bh = blockIdx.y;
    const int b  = bh / NH;
    const int h  = bh % NH;
    const int t0 = qt * 64;

    const float* qbase = qb + ((size_t)b * TQ + t0) * D_MODEL + h * HDIM;
#pragma unroll
    for (int u = 0; u < 4; u++) {
        int idx = tid + u * 256;
        int r   = idx >> 4;
        int dq  = (idx & 15) * 4;
        float4 v = *(const float4*)(qbase + (size_t)r * D_MODEL + dq);
        Qs[(dq + 0) * LDP + r] = v.x * SCALE;
        Qs[(dq + 1) * LDP + r] = v.y * SCALE;
        Qs[(dq + 2) * LDP + r] = v.z * SCALE;
        Qs[(dq + 3) * LDP + r] = v.w * SCALE;
    }

    float m_run[4], l_run[4], acc[4][4];
#pragma unroll
    for (int i = 0; i < 4; i++) {
        m_run[i] = -1e30f; l_run[i] = 0.f;
#pragma unroll
        for (int j = 0; j < 4; j++) acc[i][j] = 0.f;
    }

    for (int n0 = 0; n0 < NKV; n0 += 64) {
        const float* kbase = kb + ((size_t)b * NKV + n0) * D_MODEL + h * HDIM;
        const float* vbase = vb + ((size_t)b * NKV + n0) * D_MODEL + h * HDIM;
#pragma unroll
        for (int u = 0; u < 4; u++) {
            int idx = tid + u * 256;
            int r   = idx >> 4;
            int dq  = (idx & 15) * 4;
            float4 kv4 = *(const float4*)(kbase + (size_t)r * D_MODEL + dq);
            Ks[(dq + 0) * LDP + r] = kv4.x;
            Ks[(dq + 1) * LDP + r] = kv4.y;
            Ks[(dq + 2) * LDP + r] = kv4.z;
            Ks[(dq + 3) * LDP + r] = kv4.w;
            float4 vv4 = *(const float4*)(vbase + (size_t)r * D_MODEL + dq);
            *(float4*)&Vs[r * LDP + dq] = vv4;
        }
        __syncthreads();

        float s[4][4];
#pragma unroll
        for (int i = 0; i < 4; i++)
#pragma unroll
            for (int j = 0; j < 4; j++) s[i][j] = 0.f;
#pragma unroll 16
        for (int d = 0; d < 64; d++) {
            float4 a  = *(const float4*)&Qs[d * LDP + ty * 4];
            float4 k4 = *(const float4*)&Ks[d * LDP + tx * 4];
            float av[4]  = {a.x, a.y, a.z, a.w};
            float bv4[4] = {k4.x, k4.y, k4.z, k4.w};
#pragma unroll
            for (int i = 0; i < 4; i++)
#pragma unroll
                for (int j = 0; j < 4; j++)
                    s[i][j] += av[i] * bv4[j];
        }

        const unsigned char* mrow = mask + (size_t)b * NKV + n0 + tx * 4;
#pragma unroll
        for (int j = 0; j < 4; j++) {
            if (mrow[j]) {
#pragma unroll
                for (int i = 0; i < 4; i++) s[i][j] = -1e30f;
            }
        }

        float corr[4];
#pragma unroll
        for (int i = 0; i < 4; i++) {
            float rm = fmaxf(fmaxf(s[i][0], s[i][1]), fmaxf(s[i][2], s[i][3]));
            rm = fmaxf(rm, __shfl_xor_sync(0xffffffffu, rm, 1));
            rm = fmaxf(rm, __shfl_xor_sync(0xffffffffu, rm, 2));
            rm = fmaxf(rm, __shfl_xor_sync(0xffffffffu, rm, 4));
            rm = fmaxf(rm, __shfl_xor_sync(0xffffffffu, rm, 8));
            float mn = fmaxf(m_run[i], rm);
            corr[i] = __expf(m_run[i] - mn);
            m_run[i] = mn;
            float rs = 0.f;
#pragma unroll
            for (int j = 0; j < 4; j++) {
                float p = __expf(s[i][j] - mn);
                s[i][j] = p;
                rs += p;
            }
            rs += __shfl_xor_sync(0xffffffffu, rs, 1);
            rs += __shfl_xor_sync(0xffffffffu, rs, 2);
            rs += __shfl_xor_sync(0xffffffffu, rs, 4);
            rs += __shfl_xor_sync(0xffffffffu, rs, 8);
            l_run[i] = l_run[i] * corr[i] + rs;
        }

        __syncthreads();
        float* Ps = Ks;
#pragma unroll
        for (int j = 0; j < 4; j++) {
            float4 pv = make_float4(s[0][j], s[1][j], s[2][j], s[3][j]);
            *(float4*)&Ps[(tx * 4 + j) * LDP + ty * 4] = pv;
        }
        __syncthreads();

#pragma unroll
        for (int i = 0; i < 4; i++)
#pragma unroll
            for (int j = 0; j < 4; j++) acc[i][j] *= corr[i];
#pragma unroll 16
        for (int n = 0; n < 64; n++) {
            float4 p  = *(const float4*)&Ps[n * LDP + ty * 4];
            float4 vv = *(const float4*)&Vs[n * LDP + tx * 4];
            float pv[4]  = {p.x, p.y, p.z, p.w};
            float vvv[4] = {vv.x, vv.y, vv.z, vv.w};
#pragma unroll
            for (int i = 0; i < 4; i++)
#pragma unroll
                for (int j = 0; j < 4; j++)
                    acc[i][j] += pv[i] * vvv[j];
        }
        __syncthreads();
    }

    float* obase = ctx + ((size_t)b * TQ + t0) * D_MODEL + h * HDIM;
#pragma unroll
    for (int i = 0; i < 4; i++) {
        float inv = 1.f / l_run[i];
        float4 r;
        r.x = acc[i][0] * inv;
        r.y = acc[i][1] * inv;
        r.z = acc[i][2] * inv;
        r.w = acc[i][3] * inv;
        *(float4*)(obase + (size_t)(ty * 4 + i) * D_MODEL + tx * 4) = r;
    }
}

// ---------------------------------------------------------------------------
extern "C" void kernel_launch(void* const* d_in, const int* in_sizes, int n_in,
                              void* d_out, int out_size)
{
    const float* query = (const float*)d_in[0];
    const float* kv    = (const float*)d_in[1];
    const unsigned char* mask = (const unsigned char*)d_in[2];
    const float* Wq = (const float*)d_in[3];
    const float* bq = (const float*)d_in[4];
    const float* Wk = (const float*)d_in[5];
    const float* bk = (const float*)d_in[6];
    const float* Wv = (const float*)d_in[7];
    const float* bv = (const float*)d_in[8];
    const float* Wo = (const float*)d_in[9];
    const float* bo = (const float*)d_in[10];
    float* out = (float*)d_out;

    static float *qb = nullptr, *kb = nullptr, *vbuf = nullptr, *cb = nullptr;
    static const int SMEM_ATTN = 3 * 64 * LDP * 4;   // 52224 bytes
    if (!qb) {
        cudaGetSymbolAddress((void**)&qb,   g_q);
        cudaGetSymbolAddress((void**)&kb,   g_k);
        cudaGetSymbolAddress((void**)&vbuf, g_v);
        cudaGetSymbolAddress((void**)&cb,   g_ctx);
        cudaFuncSetAttribute(attn_kernel,
                             cudaFuncAttributeMaxDynamicSharedMemorySize, SMEM_ATTN);
    }

    dim3 blk(256);
    // Projections on tensor cores (tf32): C = A @ W^T + b
    gemm_tf32_nt_bias<<<dim3(8, 64), blk>>>(query, Wq, bq, qb,   B_ * TQ,  D_MODEL, D_MODEL);
    gemm_tf32_nt_bias<<<dim3(8, 96), blk>>>(kv,    Wk, bk, kb,   B_ * NKV, D_MODEL, D_MODEL);
    gemm_tf32_nt_bias<<<dim3(8, 96), blk>>>(kv,    Wv, bv, vbuf, B_ * NKV, D_MODEL, D_MODEL);

    // Attention (SIMT, unchanged this round)
    attn_kernel<<<dim3(TQ / 64, B_ * NH), blk, SMEM_ATTN>>>(qb, kb, vbuf, mask, cb);

    // Output projection
    gemm_tf32_nt_bias<<<dim3(8, 64), blk>>>(cb, Wo, bo, out, B_ * TQ, D_MODEL, D_MODEL);
}

// round 7
// speedup vs baseline: 2.7542x; 1.7049x over previous
#include <cuda_runtime.h>
#include <cstdint>

#define D_MODEL 1024
#define NH      16
#define HDIM    64
#define B_      8
#define TQ      1024
#define NKV     1536
#define SCALE   0.125f   // HD^-0.5

// attention tiles
#define BQ    128
#define BKV   64
#define LDS_P 68         // P/Q stage stride: 4g+tig distinct mod 32
#define LDS_K 68
#define LDS_V 72         // 8tig+g distinct mod 32

// Scratch (allocation-free rule: __device__ globals)
__device__ float g_q[B_ * TQ * D_MODEL];
__device__ float g_k[B_ * NKV * D_MODEL];
__device__ float g_v[B_ * NKV * D_MODEL];
__device__ float g_ctx[B_ * TQ * D_MODEL];

// ---------------------------------------------------------------------------
__device__ __forceinline__ float to_tf32(float x) {
    uint32_t y;
    asm("cvt.rna.tf32.f32 %0, %1;" : "=r"(y) : "f"(x));
    return __uint_as_float(y);
}

__device__ __forceinline__ void mma_tf32_16x8x8(
    float& c0, float& c1, float& c2, float& c3,
    uint32_t a0, uint32_t a1, uint32_t a2, uint32_t a3,
    uint32_t b0, uint32_t b1)
{
    asm volatile(
        "mma.sync.aligned.m16n8k8.row.col.f32.tf32.tf32.f32 "
        "{%0,%1,%2,%3}, {%4,%5,%6,%7}, {%8,%9}, {%0,%1,%2,%3};\n"
        : "+f"(c0), "+f"(c1), "+f"(c2), "+f"(c3)
        : "r"(a0), "r"(a1), "r"(a2), "r"(a3), "r"(b0), "r"(b1));
}

// ---------------------------------------------------------------------------
// Projection GEMM (unchanged from R6): C = A @ W^T + bias, tf32 tensor cores.
// ---------------------------------------------------------------------------
__global__ __launch_bounds__(256) void gemm_tf32_nt_bias(
    const float* __restrict__ A, const float* __restrict__ W,
    const float* __restrict__ bias, float* __restrict__ C,
    int M, int N, int K)
{
    __shared__ float As[128][36];
    __shared__ float Bs[128][36];

    const int tid  = threadIdx.x;
    const int wid  = tid >> 5;
    const int lane = tid & 31;
    const int g    = lane >> 2;
    const int tig  = lane & 3;
    const int warp_m = (wid >> 2) * 64;
    const int warp_n = (wid & 3) * 32;
    const int bm = blockIdx.y * 128;
    const int bn = blockIdx.x * 128;

    const int lrow = tid >> 3;
    const int lcol = (tid & 7) * 4;

    float acc[4][4][4];
#pragma unroll
    for (int mf = 0; mf < 4; mf++)
#pragma unroll
        for (int nf = 0; nf < 4; nf++)
#pragma unroll
            for (int r = 0; r < 4; r++) acc[mf][nf][r] = 0.f;

    const float* aptr = A + (size_t)(bm + lrow) * K + lcol;
    const float* bptr = W + (size_t)(bn + lrow) * K + lcol;

    float4 ra[4], rb[4];
#pragma unroll
    for (int u = 0; u < 4; u++) {
        ra[u] = *(const float4*)(aptr + (size_t)u * 32 * K);
        rb[u] = *(const float4*)(bptr + (size_t)u * 32 * K);
    }
#pragma unroll
    for (int u = 0; u < 4; u++) {
        int r = lrow + u * 32;
        As[r][lcol + 0] = to_tf32(ra[u].x); As[r][lcol + 1] = to_tf32(ra[u].y);
        As[r][lcol + 2] = to_tf32(ra[u].z); As[r][lcol + 3] = to_tf32(ra[u].w);
        Bs[r][lcol + 0] = to_tf32(rb[u].x); Bs[r][lcol + 1] = to_tf32(rb[u].y);
        Bs[r][lcol + 2] = to_tf32(rb[u].z); Bs[r][lcol + 3] = to_tf32(rb[u].w);
    }
    __syncthreads();

    const int kTiles = K >> 5;
    for (int kt = 0; kt < kTiles; kt++) {
        const bool notlast = (kt + 1 < kTiles);
        if (notlast) {
            const float* ap = aptr + (size_t)(kt + 1) * 32;
            const float* bp = bptr + (size_t)(kt + 1) * 32;
#pragma unroll
            for (int u = 0; u < 4; u++) {
                ra[u] = *(const float4*)(ap + (size_t)u * 32 * K);
                rb[u] = *(const float4*)(bp + (size_t)u * 32 * K);
            }
        }
#pragma unroll
        for (int ks = 0; ks < 4; ks++) {
            const int k0 = ks * 8;
            uint32_t af[4][4];
#pragma unroll
            for (int mf = 0; mf < 4; mf++) {
                int row = warp_m + mf * 16;
                af[mf][0] = __float_as_uint(As[row + g    ][k0 + tig    ]);
                af[mf][1] = __float_as_uint(As[row + g + 8][k0 + tig    ]);
                af[mf][2] = __float_as_uint(As[row + g    ][k0 + tig + 4]);
                af[mf][3] = __float_as_uint(As[row + g + 8][k0 + tig + 4]);
            }
            uint32_t bf[4][2];
#pragma unroll
            for (int nf = 0; nf < 4; nf++) {
                int col = warp_n + nf * 8;
                bf[nf][0] = __float_as_uint(Bs[col + g][k0 + tig    ]);
                bf[nf][1] = __float_as_uint(Bs[col + g][k0 + tig + 4]);
            }
#pragma unroll
            for (int mf = 0; mf < 4; mf++)
#pragma unroll
                for (int nf = 0; nf < 4; nf++)
                    mma_tf32_16x8x8(acc[mf][nf][0], acc[mf][nf][1],
                                    acc[mf][nf][2], acc[mf][nf][3],
                                    af[mf][0], af[mf][1], af[mf][2], af[mf][3],
                                    bf[nf][0], bf[nf][1]);
        }
        __syncthreads();
        if (notlast) {
#pragma unroll
            for (int u = 0; u < 4; u++) {
                int r = lrow + u * 32;
                As[r][lcol + 0] = to_tf32(ra[u].x); As[r][lcol + 1] = to_tf32(ra[u].y);
                As[r][lcol + 2] = to_tf32(ra[u].z); As[r][lcol + 3] = to_tf32(ra[u].w);
                Bs[r][lcol + 0] = to_tf32(rb[u].x); Bs[r][lcol + 1] = to_tf32(rb[u].y);
                Bs[r][lcol + 2] = to_tf32(rb[u].z); Bs[r][lcol + 3] = to_tf32(rb[u].w);
            }
            __syncthreads();
        }
    }

#pragma unroll
    for (int mf = 0; mf < 4; mf++) {
        int row0 = bm + warp_m + mf * 16 + g;
#pragma unroll
        for (int nf = 0; nf < 4; nf++) {
            int col = bn + warp_n + nf * 8 + 2 * tig;
            float bv0 = bias[col], bv1 = bias[col + 1];
            *(float2*)&C[(size_t)row0 * N + col] =
                make_float2(acc[mf][nf][0] + bv0, acc[mf][nf][1] + bv1);
            *(float2*)&C[(size_t)(row0 + 8) * N + col] =
                make_float2(acc[mf][nf][2] + bv0, acc[mf][nf][3] + bv1);
        }
    }
}

// ---------------------------------------------------------------------------
// Tensor-core flash attention.
// grid (TQ/128, B*H), 256 threads = 8 warps. Warp w owns q rows [16w,16w+16).
// S = Q@K^T via m16n8k8 tf32 (Q frags register-resident, loaded once);
// warp-local online softmax; P->smem (syncwarp only); O += P@V via mma.
// ---------------------------------------------------------------------------
__global__ __launch_bounds__(256) void attn_tc_kernel(
    const float* __restrict__ qb, const float* __restrict__ kb,
    const float* __restrict__ vb, const unsigned char* __restrict__ mask,
    float* __restrict__ ctx)
{
    extern __shared__ float sm[];
    float* Ps = sm;                        // [128][LDS_P]  Q stage, then P
    float* Ks = Ps + BQ * LDS_P;           // [64][LDS_K]
    float* Vs = Ks + BKV * LDS_K;          // [64][LDS_V]
    unsigned char* Ms = (unsigned char*)(Vs + BKV * LDS_V);   // [64]

    const int tid  = threadIdx.x;
    const int wid  = tid >> 5;
    const int lane = tid & 31;
    const int g    = lane >> 2;       // 0..7
    const int tig  = lane & 3;        // 0..3
    const int qr0  = wid * 16;        // warp's q-row slab
    const int b = blockIdx.y / NH;
    const int h = blockIdx.y % NH;
    const int t0 = blockIdx.x * BQ;

    // ---- stage Q*SCALE (tf32) ----
    const float* qbase = qb + ((size_t)b * TQ + t0) * D_MODEL + h * HDIM;
#pragma unroll
    for (int u = 0; u < 8; u++) {
        int idx = tid + u * 256;          // 0..2047
        int r = idx >> 4, c = (idx & 15) * 4;
        float4 v = *(const float4*)(qbase + (size_t)r * D_MODEL + c);
        float* dst = &Ps[r * LDS_P + c];
        dst[0] = to_tf32(v.x * SCALE); dst[1] = to_tf32(v.y * SCALE);
        dst[2] = to_tf32(v.z * SCALE); dst[3] = to_tf32(v.w * SCALE);
    }
    __syncthreads();

    // ---- Q fragments to registers (reused for all KV tiles) ----
    uint32_t qa[8][4];
#pragma unroll
    for (int ks = 0; ks < 8; ks++) {
        int k0 = ks * 8;
        qa[ks][0] = __float_as_uint(Ps[(qr0 + g    ) * LDS_P + k0 + tig    ]);
        qa[ks][1] = __float_as_uint(Ps[(qr0 + g + 8) * LDS_P + k0 + tig    ]);
        qa[ks][2] = __float_as_uint(Ps[(qr0 + g    ) * LDS_P + k0 + tig + 4]);
        qa[ks][3] = __float_as_uint(Ps[(qr0 + g + 8) * LDS_P + k0 + tig + 4]);
    }

    float m0 = -1e30f, m1 = -1e30f, l0 = 0.f, l1 = 0.f;
    float o[8][4];
#pragma unroll
    for (int df = 0; df < 8; df++)
#pragma unroll
        for (int r = 0; r < 4; r++) o[df][r] = 0.f;

    for (int n0 = 0; n0 < NKV; n0 += BKV) {
        // ---- stage K, V (tf32), mask ----
        const float* kbase = kb + ((size_t)b * NKV + n0) * D_MODEL + h * HDIM;
        const float* vbase = vb + ((size_t)b * NKV + n0) * D_MODEL + h * HDIM;
#pragma unroll
        for (int u = 0; u < 4; u++) {
            int idx = tid + u * 256;      // 0..1023
            int r = idx >> 4, c = (idx & 15) * 4;
            float4 k4 = *(const float4*)(kbase + (size_t)r * D_MODEL + c);
            float* kd = &Ks[r * LDS_K + c];
            kd[0] = to_tf32(k4.x); kd[1] = to_tf32(k4.y);
            kd[2] = to_tf32(k4.z); kd[3] = to_tf32(k4.w);
            float4 v4 = *(const float4*)(vbase + (size_t)r * D_MODEL + c);
            float* vd = &Vs[r * LDS_V + c];
            vd[0] = to_tf32(v4.x); vd[1] = to_tf32(v4.y);
            vd[2] = to_tf32(v4.z); vd[3] = to_tf32(v4.w);
        }
        if (tid < 16)
            ((uint32_t*)Ms)[tid] =
                *(const uint32_t*)(mask + (size_t)b * NKV + n0 + tid * 4);
        __syncthreads();

        // ---- S = Q @ K^T : 16 x 64 per warp ----
        float s[8][4];
#pragma unroll
        for (int nf = 0; nf < 8; nf++) {
            s[nf][0] = 0.f; s[nf][1] = 0.f; s[nf][2] = 0.f; s[nf][3] = 0.f;
#pragma unroll
            for (int ks = 0; ks < 8; ks++) {
                int k0 = ks * 8;
                uint32_t b0 = __float_as_uint(Ks[(nf * 8 + g) * LDS_K + k0 + tig    ]);
                uint32_t b1 = __float_as_uint(Ks[(nf * 8 + g) * LDS_K + k0 + tig + 4]);
                mma_tf32_16x8x8(s[nf][0], s[nf][1], s[nf][2], s[nf][3],
                                qa[ks][0], qa[ks][1], qa[ks][2], qa[ks][3], b0, b1);
            }
        }

        // ---- mask ----
#pragma unroll
        for (int nf = 0; nf < 8; nf++) {
            int c0 = nf * 8 + 2 * tig;
            if (Ms[c0])     { s[nf][0] = -1e30f; s[nf][2] = -1e30f; }
            if (Ms[c0 + 1]) { s[nf][1] = -1e30f; s[nf][3] = -1e30f; }
        }

        // ---- warp-local online softmax (rows qr0+g and qr0+g+8) ----
        float rmax0 = -1e30f, rmax1 = -1e30f;
#pragma unroll
        for (int nf = 0; nf < 8; nf++) {
            rmax0 = fmaxf(rmax0, fmaxf(s[nf][0], s[nf][1]));
            rmax1 = fmaxf(rmax1, fmaxf(s[nf][2], s[nf][3]));
        }
        rmax0 = fmaxf(rmax0, __shfl_xor_sync(0xffffffffu, rmax0, 1));
        rmax0 = fmaxf(rmax0, __shfl_xor_sync(0xffffffffu, rmax0, 2));
        rmax1 = fmaxf(rmax1, __shfl_xor_sync(0xffffffffu, rmax1, 1));
        rmax1 = fmaxf(rmax1, __shfl_xor_sync(0xffffffffu, rmax1, 2));

        float mn0 = fmaxf(m0, rmax0), mn1 = fmaxf(m1, rmax1);
        float corr0 = __expf(m0 - mn0), corr1 = __expf(m1 - mn1);
        m0 = mn0; m1 = mn1;

        float rs0 = 0.f, rs1 = 0.f;
#pragma unroll
        for (int nf = 0; nf < 8; nf++) {
            s[nf][0] = __expf(s[nf][0] - mn0); rs0 += s[nf][0];
            s[nf][1] = __expf(s[nf][1] - mn0); rs0 += s[nf][1];
            s[nf][2] = __expf(s[nf][2] - mn1); rs1 += s[nf][2];
            s[nf][3] = __expf(s[nf][3] - mn1); rs1 += s[nf][3];
        }
        rs0 += __shfl_xor_sync(0xffffffffu, rs0, 1);
        rs0 += __shfl_xor_sync(0xffffffffu, rs0, 2);
        rs1 += __shfl_xor_sync(0xffffffffu, rs1, 1);
        rs1 += __shfl_xor_sync(0xffffffffu, rs1, 2);
        l0 = l0 * corr0 + rs0;
        l1 = l1 * corr1 + rs1;

        // ---- P -> smem (warp-private rows; syncwarp suffices) ----
#pragma unroll
        for (int nf = 0; nf < 8; nf++) {
            int col = nf * 8 + 2 * tig;
            *(float2*)&Ps[(qr0 + g    ) * LDS_P + col] =
                make_float2(to_tf32(s[nf][0]), to_tf32(s[nf][1]));
            *(float2*)&Ps[(qr0 + g + 8) * LDS_P + col] =
                make_float2(to_tf32(s[nf][2]), to_tf32(s[nf][3]));
        }
        __syncwarp();

        // ---- O = O*corr + P @ V ----
#pragma unroll
        for (int df = 0; df < 8; df++) {
            o[df][0] *= corr0; o[df][1] *= corr0;
            o[df][2] *= corr1; o[df][3] *= corr1;
        }
#pragma unroll
        for (int ks = 0; ks < 8; ks++) {
            int k0 = ks * 8;
            uint32_t pa0 = __float_as_uint(Ps[(qr0 + g    ) * LDS_P + k0 + tig    ]);
            uint32_t pa1 = __float_as_uint(Ps[(qr0 + g + 8) * LDS_P + k0 + tig    ]);
            uint32_t pa2 = __float_as_uint(Ps[(qr0 + g    ) * LDS_P + k0 + tig + 4]);
            uint32_t pa3 = __float_as_uint(Ps[(qr0 + g + 8) * LDS_P + k0 + tig + 4]);
#pragma unroll
            for (int df = 0; df < 8; df++) {
                uint32_t vb0 = __float_as_uint(Vs[(k0 + tig    ) * LDS_V + df * 8 + g]);
                uint32_t vb1 = __float_as_uint(Vs[(k0 + tig + 4) * LDS_V + df * 8 + g]);
                mma_tf32_16x8x8(o[df][0], o[df][1], o[df][2], o[df][3],
                                pa0, pa1, pa2, pa3, vb0, vb1);
            }
        }
        __syncthreads();   // protect Ks/Vs (and P rows) before next staging
    }

    // ---- normalize, write ----
    float inv0 = 1.f / l0, inv1 = 1.f / l1;
    float* obase = ctx + ((size_t)b * TQ + t0) * D_MODEL + h * HDIM;
#pragma unroll
    for (int df = 0; df < 8; df++) {
        int col = df * 8 + 2 * tig;
        *(float2*)&obase[(size_t)(qr0 + g    ) * D_MODEL + col] =
            make_float2(o[df][0] * inv0, o[df][1] * inv0);
        *(float2*)&obase[(size_t)(qr0 + g + 8) * D_MODEL + col] =
            make_float2(o[df][2] * inv1, o[df][3] * inv1);
    }
}

// ---------------------------------------------------------------------------
extern "C" void kernel_launch(void* const* d_in, const int* in_sizes, int n_in,
                              void* d_out, int out_size)
{
    const float* query = (const float*)d_in[0];
    const float* kv    = (const float*)d_in[1];
    const unsigned char* mask = (const unsigned char*)d_in[2];
    const float* Wq = (const float*)d_in[3];
    const float* bq = (const float*)d_in[4];
    const float* Wk = (const float*)d_in[5];
    const float* bk = (const float*)d_in[6];
    const float* Wv = (const float*)d_in[7];
    const float* bv = (const float*)d_in[8];
    const float* Wo = (const float*)d_in[9];
    const float* bo = (const float*)d_in[10];
    float* out = (float*)d_out;

    static float *qb = nullptr, *kb = nullptr, *vbuf = nullptr, *cb = nullptr;
    static const int SMEM_ATTN =
        (BQ * LDS_P + BKV * LDS_K + BKV * LDS_V) * 4 + 64;   // 70720 B
    if (!qb) {
        cudaGetSymbolAddress((void**)&qb,   g_q);
        cudaGetSymbolAddress((void**)&kb,   g_k);
        cudaGetSymbolAddress((void**)&vbuf, g_v);
        cudaGetSymbolAddress((void**)&cb,   g_ctx);
        cudaFuncSetAttribute(attn_tc_kernel,
                             cudaFuncAttributeMaxDynamicSharedMemorySize, SMEM_ATTN);
    }

    dim3 blk(256);
    gemm_tf32_nt_bias<<<dim3(8, 64), blk>>>(query, Wq, bq, qb,   B_ * TQ,  D_MODEL, D_MODEL);
    gemm_tf32_nt_bias<<<dim3(8, 96), blk>>>(kv,    Wk, bk, kb,   B_ * NKV, D_MODEL, D_MODEL);
    gemm_tf32_nt_bias<<<dim3(8, 96), blk>>>(kv,    Wv, bv, vbuf, B_ * NKV, D_MODEL, D_MODEL);

    attn_tc_kernel<<<dim3(TQ / BQ, B_ * NH), blk, SMEM_ATTN>>>(qb, kb, vbuf, mask, cb);

    gemm_tf32_nt_bias<<<dim3(8, 64), blk>>>(cb, Wo, bo, out, B_ * TQ, D_MODEL, D_MODEL);
}

// round 8
// speedup vs baseline: 2.9919x; 1.0863x over previous
#include <cuda_runtime.h>
#include <cstdint>

#define D_MODEL 1024
#define NH      16
#define HDIM    64
#define B_      8
#define TQ      1024
#define NKV     1536
#define SCALE   0.125f   // HD^-0.5

// attention tiles
#define BQ    128
#define BKV   64
#define LDS_P 68
#define LDS_K 68
#define LDS_V 72

// Scratch (allocation-free rule: __device__ globals)
__device__ float g_q[B_ * TQ * D_MODEL];
__device__ float g_k[B_ * NKV * D_MODEL];
__device__ float g_v[B_ * NKV * D_MODEL];
__device__ float g_ctx[B_ * TQ * D_MODEL];

// ---------------------------------------------------------------------------
__device__ __forceinline__ float to_tf32(float x) {
    uint32_t y;
    asm("cvt.rna.tf32.f32 %0, %1;" : "=r"(y) : "f"(x));
    return __uint_as_float(y);
}

__device__ __forceinline__ void mma_tf32_16x8x8(
    float& c0, float& c1, float& c2, float& c3,
    uint32_t a0, uint32_t a1, uint32_t a2, uint32_t a3,
    uint32_t b0, uint32_t b1)
{
    asm volatile(
        "mma.sync.aligned.m16n8k8.row.col.f32.tf32.tf32.f32 "
        "{%0,%1,%2,%3}, {%4,%5,%6,%7}, {%8,%9}, {%0,%1,%2,%3};\n"
        : "+f"(c0), "+f"(c1), "+f"(c2), "+f"(c3)
        : "r"(a0), "r"(a1), "r"(a2), "r"(a3), "r"(b0), "r"(b1));
}

// ---------------------------------------------------------------------------
// Projection GEMM, tf32 tensor cores, double-buffered smem (1 barrier/tile).
// C = A @ W^T + bias. BM=BN=128, BK=32, 8 warps, warp tile 64x32.
// ---------------------------------------------------------------------------
__global__ __launch_bounds__(256) void gemm_tf32_nt_bias(
    const float* __restrict__ A, const float* __restrict__ W,
    const float* __restrict__ bias, float* __restrict__ C,
    int M, int N, int K)
{
    extern __shared__ float gsm[];
    float* As = gsm;                    // [2][128][36]
    float* Bs = gsm + 2 * 128 * 36;     // [2][128][36]

    const int tid  = threadIdx.x;
    const int wid  = tid >> 5;
    const int lane = tid & 31;
    const int g    = lane >> 2;
    const int tig  = lane & 3;
    const int warp_m = (wid >> 2) * 64;
    const int warp_n = (wid & 3) * 32;
    const int bm = blockIdx.y * 128;
    const int bn = blockIdx.x * 128;

    const int lrow = tid >> 3;
    const int lcol = (tid & 7) * 4;

    float acc[4][4][4];
#pragma unroll
    for (int mf = 0; mf < 4; mf++)
#pragma unroll
        for (int nf = 0; nf < 4; nf++)
#pragma unroll
            for (int r = 0; r < 4; r++) acc[mf][nf][r] = 0.f;

    const float* aptr = A + (size_t)(bm + lrow) * K + lcol;
    const float* bptr = W + (size_t)(bn + lrow) * K + lcol;

    float4 ra[4], rb[4];
    // prologue: tile 0 -> buf 0
#pragma unroll
    for (int u = 0; u < 4; u++) {
        ra[u] = *(const float4*)(aptr + (size_t)u * 32 * K);
        rb[u] = *(const float4*)(bptr + (size_t)u * 32 * K);
    }
#pragma unroll
    for (int u = 0; u < 4; u++) {
        int r = lrow + u * 32;
        float* ad = &As[r * 36 + lcol];
        float* bd = &Bs[r * 36 + lcol];
        ad[0] = to_tf32(ra[u].x); ad[1] = to_tf32(ra[u].y);
        ad[2] = to_tf32(ra[u].z); ad[3] = to_tf32(ra[u].w);
        bd[0] = to_tf32(rb[u].x); bd[1] = to_tf32(rb[u].y);
        bd[2] = to_tf32(rb[u].z); bd[3] = to_tf32(rb[u].w);
    }
    __syncthreads();

    const int kTiles = K >> 5;
    for (int kt = 0; kt < kTiles; kt++) {
        const int cur = (kt & 1) * 128 * 36;
        const int nxt = ((kt + 1) & 1) * 128 * 36;
        const bool pf = (kt + 1 < kTiles);
        if (pf) {
            const float* ap = aptr + (size_t)(kt + 1) * 32;
            const float* bp = bptr + (size_t)(kt + 1) * 32;
#pragma unroll
            for (int u = 0; u < 4; u++) {
                ra[u] = *(const float4*)(ap + (size_t)u * 32 * K);
                rb[u] = *(const float4*)(bp + (size_t)u * 32 * K);
            }
        }
#pragma unroll
        for (int ks = 0; ks < 4; ks++) {
            const int k0 = ks * 8;
            uint32_t af[4][4];
#pragma unroll
            for (int mf = 0; mf < 4; mf++) {
                int row = warp_m + mf * 16;
                af[mf][0] = __float_as_uint(As[cur + (row + g    ) * 36 + k0 + tig    ]);
                af[mf][1] = __float_as_uint(As[cur + (row + g + 8) * 36 + k0 + tig    ]);
                af[mf][2] = __float_as_uint(As[cur + (row + g    ) * 36 + k0 + tig + 4]);
                af[mf][3] = __float_as_uint(As[cur + (row + g + 8) * 36 + k0 + tig + 4]);
            }
            uint32_t bf[4][2];
#pragma unroll
            for (int nf = 0; nf < 4; nf++) {
                int col = warp_n + nf * 8;
                bf[nf][0] = __float_as_uint(Bs[cur + (col + g) * 36 + k0 + tig    ]);
                bf[nf][1] = __float_as_uint(Bs[cur + (col + g) * 36 + k0 + tig + 4]);
            }
#pragma unroll
            for (int mf = 0; mf < 4; mf++)
#pragma unroll
                for (int nf = 0; nf < 4; nf++)
                    mma_tf32_16x8x8(acc[mf][nf][0], acc[mf][nf][1],
                                    acc[mf][nf][2], acc[mf][nf][3],
                                    af[mf][0], af[mf][1], af[mf][2], af[mf][3],
                                    bf[nf][0], bf[nf][1]);
        }
        if (pf) {
#pragma unroll
            for (int u = 0; u < 4; u++) {
                int r = lrow + u * 32;
                float* ad = &As[nxt + r * 36 + lcol];
                float* bd = &Bs[nxt + r * 36 + lcol];
                ad[0] = to_tf32(ra[u].x); ad[1] = to_tf32(ra[u].y);
                ad[2] = to_tf32(ra[u].z); ad[3] = to_tf32(ra[u].w);
                bd[0] = to_tf32(rb[u].x); bd[1] = to_tf32(rb[u].y);
                bd[2] = to_tf32(rb[u].z); bd[3] = to_tf32(rb[u].w);
            }
        }
        __syncthreads();
    }

#pragma unroll
    for (int mf = 0; mf < 4; mf++) {
        int row0 = bm + warp_m + mf * 16 + g;
#pragma unroll
        for (int nf = 0; nf < 4; nf++) {
            int col = bn + warp_n + nf * 8 + 2 * tig;
            float bv0 = bias[col], bv1 = bias[col + 1];
            *(float2*)&C[(size_t)row0 * N + col] =
                make_float2(acc[mf][nf][0] + bv0, acc[mf][nf][1] + bv1);
            *(float2*)&C[(size_t)(row0 + 8) * N + col] =
                make_float2(acc[mf][nf][2] + bv0, acc[mf][nf][3] + bv1);
        }
    }
}

// ---------------------------------------------------------------------------
// Tensor-core flash attention, double-buffered K/V (1 barrier/tile).
// grid (TQ/128, B*H), 8 warps; warp w owns q rows [16w,16w+16).
// ---------------------------------------------------------------------------
__global__ __launch_bounds__(256) void attn_tc_kernel(
    const float* __restrict__ qb, const float* __restrict__ kb,
    const float* __restrict__ vb, const unsigned char* __restrict__ mask,
    float* __restrict__ ctx)
{
    extern __shared__ float sm[];
    float* Ps = sm;                          // [128][LDS_P]  Q stage, then P
    float* Ks = Ps + BQ * LDS_P;             // [2][64][LDS_K]
    float* Vs = Ks + 2 * BKV * LDS_K;        // [2][64][LDS_V]
    unsigned char* Ms = (unsigned char*)(Vs + 2 * BKV * LDS_V);  // [2][64]

    const int tid  = threadIdx.x;
    const int wid  = tid >> 5;
    const int lane = tid & 31;
    const int g    = lane >> 2;
    const int tig  = lane & 3;
    const int qr0  = wid * 16;
    const int b = blockIdx.y / NH;
    const int h = blockIdx.y % NH;
    const int t0 = blockIdx.x * BQ;

    const int sr = tid >> 4;            // 0..15 staging row group
    const int sc = (tid & 15) * 4;      // 0..60 staging col

    // ---- stage Q*SCALE (tf32) ----
    const float* qbase = qb + ((size_t)b * TQ + t0) * D_MODEL + h * HDIM;
#pragma unroll
    for (int u = 0; u < 8; u++) {
        int idx = tid + u * 256;
        int r = idx >> 4, c = (idx & 15) * 4;
        float4 v = *(const float4*)(qbase + (size_t)r * D_MODEL + c);
        float* dst = &Ps[r * LDS_P + c];
        dst[0] = to_tf32(v.x * SCALE); dst[1] = to_tf32(v.y * SCALE);
        dst[2] = to_tf32(v.z * SCALE); dst[3] = to_tf32(v.w * SCALE);
    }

    const float* kbase = kb + ((size_t)b * NKV) * D_MODEL + h * HDIM;
    const float* vbase = vb + ((size_t)b * NKV) * D_MODEL + h * HDIM;
    const unsigned char* mbase = mask + (size_t)b * NKV;

    // ---- prologue: KV tile 0 -> buf 0 ----
#pragma unroll
    for (int u = 0; u < 4; u++) {
        int r = sr + u * 16;
        float4 k4 = *(const float4*)(kbase + (size_t)r * D_MODEL + sc);
        float4 v4 = *(const float4*)(vbase + (size_t)r * D_MODEL + sc);
        float* kd = &Ks[r * LDS_K + sc];
        float* vd = &Vs[r * LDS_V + sc];
        kd[0] = to_tf32(k4.x); kd[1] = to_tf32(k4.y);
        kd[2] = to_tf32(k4.z); kd[3] = to_tf32(k4.w);
        vd[0] = to_tf32(v4.x); vd[1] = to_tf32(v4.y);
        vd[2] = to_tf32(v4.z); vd[3] = to_tf32(v4.w);
    }
    if (tid < 16)
        ((uint32_t*)Ms)[tid] = *(const uint32_t*)(mbase + tid * 4);
    __syncthreads();

    // ---- Q fragments to registers ----
    uint32_t qa[8][4];
#pragma unroll
    for (int ks = 0; ks < 8; ks++) {
        int k0 = ks * 8;
        qa[ks][0] = __float_as_uint(Ps[(qr0 + g    ) * LDS_P + k0 + tig    ]);
        qa[ks][1] = __float_as_uint(Ps[(qr0 + g + 8) * LDS_P + k0 + tig    ]);
        qa[ks][2] = __float_as_uint(Ps[(qr0 + g    ) * LDS_P + k0 + tig + 4]);
        qa[ks][3] = __float_as_uint(Ps[(qr0 + g + 8) * LDS_P + k0 + tig + 4]);
    }

    float m0 = -1e30f, m1 = -1e30f, l0 = 0.f, l1 = 0.f;
    float o[8][4];
#pragma unroll
    for (int df = 0; df < 8; df++)
#pragma unroll
        for (int r = 0; r < 4; r++) o[df][r] = 0.f;

    const int nTiles = NKV / BKV;
    for (int t = 0; t < nTiles; t++) {
        const int cK = (t & 1) * BKV * LDS_K;
        const int cV = (t & 1) * BKV * LDS_V;
        const int cM = (t & 1) * BKV;
        const int nK = ((t + 1) & 1) * BKV * LDS_K;
        const int nV = ((t + 1) & 1) * BKV * LDS_V;
        const int nM = ((t + 1) & 1) * BKV;
        const bool pf = (t + 1 < nTiles);

        // ---- S = Q @ K^T ----
        float s[8][4];
#pragma unroll
        for (int nf = 0; nf < 8; nf++) {
            s[nf][0] = 0.f; s[nf][1] = 0.f; s[nf][2] = 0.f; s[nf][3] = 0.f;
#pragma unroll
            for (int ks = 0; ks < 8; ks++) {
                int k0 = ks * 8;
                uint32_t b0 = __float_as_uint(Ks[cK + (nf * 8 + g) * LDS_K + k0 + tig    ]);
                uint32_t b1 = __float_as_uint(Ks[cK + (nf * 8 + g) * LDS_K + k0 + tig + 4]);
                mma_tf32_16x8x8(s[nf][0], s[nf][1], s[nf][2], s[nf][3],
                                qa[ks][0], qa[ks][1], qa[ks][2], qa[ks][3], b0, b1);
            }
        }

        // ---- prefetch next KV tile (LDG overlaps softmax + PV) ----
        float4 rk[4], rv[4];
        uint32_t mword = 0;
        if (pf) {
            const float* kp = kbase + (size_t)(t + 1) * BKV * D_MODEL;
            const float* vp = vbase + (size_t)(t + 1) * BKV * D_MODEL;
#pragma unroll
            for (int u = 0; u < 4; u++) {
                int r = sr + u * 16;
                rk[u] = *(const float4*)(kp + (size_t)r * D_MODEL + sc);
                rv[u] = *(const float4*)(vp + (size_t)r * D_MODEL + sc);
            }
            if (tid < 16)
                mword = *(const uint32_t*)(mbase + (t + 1) * BKV + tid * 4);
        }

        // ---- mask ----
#pragma unroll
        for (int nf = 0; nf < 8; nf++) {
            int c0 = cM + nf * 8 + 2 * tig;
            if (Ms[c0])     { s[nf][0] = -1e30f; s[nf][2] = -1e30f; }
            if (Ms[c0 + 1]) { s[nf][1] = -1e30f; s[nf][3] = -1e30f; }
        }

        // ---- warp-local online softmax ----
        float rmax0 = -1e30f, rmax1 = -1e30f;
#pragma unroll
        for (int nf = 0; nf < 8; nf++) {
            rmax0 = fmaxf(rmax0, fmaxf(s[nf][0], s[nf][1]));
            rmax1 = fmaxf(rmax1, fmaxf(s[nf][2], s[nf][3]));
        }
        rmax0 = fmaxf(rmax0, __shfl_xor_sync(0xffffffffu, rmax0, 1));
        rmax0 = fmaxf(rmax0, __shfl_xor_sync(0xffffffffu, rmax0, 2));
        rmax1 = fmaxf(rmax1, __shfl_xor_sync(0xffffffffu, rmax1, 1));
        rmax1 = fmaxf(rmax1, __shfl_xor_sync(0xffffffffu, rmax1, 2));

        float mn0 = fmaxf(m0, rmax0), mn1 = fmaxf(m1, rmax1);
        float corr0 = __expf(m0 - mn0), corr1 = __expf(m1 - mn1);
        m0 = mn0; m1 = mn1;

        float rs0 = 0.f, rs1 = 0.f;
#pragma unroll
        for (int nf = 0; nf < 8; nf++) {
            s[nf][0] = __expf(s[nf][0] - mn0); rs0 += s[nf][0];
            s[nf][1] = __expf(s[nf][1] - mn0); rs0 += s[nf][1];
            s[nf][2] = __expf(s[nf][2] - mn1); rs1 += s[nf][2];
            s[nf][3] = __expf(s[nf][3] - mn1); rs1 += s[nf][3];
        }
        rs0 += __shfl_xor_sync(0xffffffffu, rs0, 1);
        rs0 += __shfl_xor_sync(0xffffffffu, rs0, 2);
        rs1 += __shfl_xor_sync(0xffffffffu, rs1, 1);
        rs1 += __shfl_xor_sync(0xffffffffu, rs1, 2);
        l0 = l0 * corr0 + rs0;
        l1 = l1 * corr1 + rs1;

        // ---- P -> smem (warp-private rows) ----
#pragma unroll
        for (int nf = 0; nf < 8; nf++) {
            int col = nf * 8 + 2 * tig;
            *(float2*)&Ps[(qr0 + g    ) * LDS_P + col] =
                make_float2(to_tf32(s[nf][0]), to_tf32(s[nf][1]));
            *(float2*)&Ps[(qr0 + g + 8) * LDS_P + col] =
                make_float2(to_tf32(s[nf][2]), to_tf32(s[nf][3]));
        }
        __syncwarp();

        // ---- O = O*corr + P @ V ----
#pragma unroll
        for (int df = 0; df < 8; df++) {
            o[df][0] *= corr0; o[df][1] *= corr0;
            o[df][2] *= corr1; o[df][3] *= corr1;
        }
#pragma unroll
        for (int ks = 0; ks < 8; ks++) {
            int k0 = ks * 8;
            uint32_t pa0 = __float_as_uint(Ps[(qr0 + g    ) * LDS_P + k0 + tig    ]);
            uint32_t pa1 = __float_as_uint(Ps[(qr0 + g + 8) * LDS_P + k0 + tig    ]);
            uint32_t pa2 = __float_as_uint(Ps[(qr0 + g    ) * LDS_P + k0 + tig + 4]);
            uint32_t pa3 = __float_as_uint(Ps[(qr0 + g + 8) * LDS_P + k0 + tig + 4]);
#pragma unroll
            for (int df = 0; df < 8; df++) {
                uint32_t vb0 = __float_as_uint(Vs[cV + (k0 + tig    ) * LDS_V + df * 8 + g]);
                uint32_t vb1 = __float_as_uint(Vs[cV + (k0 + tig + 4) * LDS_V + df * 8 + g]);
                mma_tf32_16x8x8(o[df][0], o[df][1], o[df][2], o[df][3],
                                pa0, pa1, pa2, pa3, vb0, vb1);
            }
        }

        // ---- store prefetched tile into idle buffer ----
        if (pf) {
#pragma unroll
            for (int u = 0; u < 4; u++) {
                int r = sr + u * 16;
                float* kd = &Ks[nK + r * LDS_K + sc];
                float* vd = &Vs[nV + r * LDS_V + sc];
                kd[0] = to_tf32(rk[u].x); kd[1] = to_tf32(rk[u].y);
                kd[2] = to_tf32(rk[u].z); kd[3] = to_tf32(rk[u].w);
                vd[0] = to_tf32(rv[u].x); vd[1] = to_tf32(rv[u].y);
                vd[2] = to_tf32(rv[u].z); vd[3] = to_tf32(rv[u].w);
            }
            if (tid < 16)
                ((uint32_t*)(Ms + nM))[tid] = mword;
        }
        __syncthreads();
    }

    // ---- normalize, write ----
    float inv0 = 1.f / l0, inv1 = 1.f / l1;
    float* obase = ctx + ((size_t)b * TQ + t0) * D_MODEL + h * HDIM;
#pragma unroll
    for (int df = 0; df < 8; df++) {
        int col = df * 8 + 2 * tig;
        *(float2*)&obase[(size_t)(qr0 + g    ) * D_MODEL + col] =
            make_float2(o[df][0] * inv0, o[df][1] * inv0);
        *(float2*)&obase[(size_t)(qr0 + g + 8) * D_MODEL + col] =
            make_float2(o[df][2] * inv1, o[df][3] * inv1);
    }
}

// ---------------------------------------------------------------------------
extern "C" void kernel_launch(void* const* d_in, const int* in_sizes, int n_in,
                              void* d_out, int out_size)
{
    const float* query = (const float*)d_in[0];
    const float* kv    = (const float*)d_in[1];
    const unsigned char* mask = (const unsigned char*)d_in[2];
    const float* Wq = (const float*)d_in[3];
    const float* bq = (const float*)d_in[4];
    const float* Wk = (const float*)d_in[5];
    const float* bk = (const float*)d_in[6];
    const float* Wv = (const float*)d_in[7];
    const float* bv = (const float*)d_in[8];
    const float* Wo = (const float*)d_in[9];
    const float* bo = (const float*)d_in[10];
    float* out = (float*)d_out;

    static float *qb = nullptr, *kb = nullptr, *vbuf = nullptr, *cb = nullptr;
    static const int SMEM_GEMM = 4 * 128 * 36 * 4;                   // 73728 B
    static const int SMEM_ATTN =
        (BQ * LDS_P + 2 * BKV * LDS_K + 2 * BKV * LDS_V) * 4 + 128;  // 106624 B
    if (!qb) {
        cudaGetSymbolAddress((void**)&qb,   g_q);
        cudaGetSymbolAddress((void**)&kb,   g_k);
        cudaGetSymbolAddress((void**)&vbuf, g_v);
        cudaGetSymbolAddress((void**)&cb,   g_ctx);
        cudaFuncSetAttribute(gemm_tf32_nt_bias,
                             cudaFuncAttributeMaxDynamicSharedMemorySize, SMEM_GEMM);
        cudaFuncSetAttribute(attn_tc_kernel,
                             cudaFuncAttributeMaxDynamicSharedMemorySize, SMEM_ATTN);
    }

    dim3 blk(256);
    gemm_tf32_nt_bias<<<dim3(8, 64), blk, SMEM_GEMM>>>(query, Wq, bq, qb,   B_ * TQ,  D_MODEL, D_MODEL);
    gemm_tf32_nt_bias<<<dim3(8, 96), blk, SMEM_GEMM>>>(kv,    Wk, bk, kb,   B_ * NKV, D_MODEL, D_MODEL);
    gemm_tf32_nt_bias<<<dim3(8, 96), blk, SMEM_GEMM>>>(kv,    Wv, bv, vbuf, B_ * NKV, D_MODEL, D_MODEL);

    attn_tc_kernel<<<dim3(TQ / BQ, B_ * NH), blk, SMEM_ATTN>>>(qb, kb, vbuf, mask, cb);

    gemm_tf32_nt_bias<<<dim3(8, 64), blk, SMEM_GEMM>>>(cb, Wo, bo, out, B_ * TQ, D_MODEL, D_MODEL);
}

// round 10
// speedup vs baseline: 3.0786x; 1.0290x over previous
#include <cuda_runtime.h>
#include <cstdint>

#define D_MODEL 1024
#define NH      16
#define HDIM    64
#define B_      8
#define TQ      1024
#define NKV     1536
#define SCALE   0.125f   // HD^-0.5 (exact power of two)

// attention tiles
#define BQ     128
#define BKV    64
#define LDS_P  68
#define LDS_K  68
#define LDS_V  72
#define STAGES 3

// Scratch (allocation-free rule: __device__ globals)
__device__ float g_q[B_ * TQ * D_MODEL];     // tf32(q*SCALE)
__device__ float g_k[B_ * NKV * D_MODEL];    // tf32(k)
__device__ float g_v[B_ * NKV * D_MODEL];    // tf32(v)
__device__ float g_ctx[B_ * TQ * D_MODEL];   // fp32 attention out

// ---------------------------------------------------------------------------
__device__ __forceinline__ float to_tf32(float x) {
    uint32_t y;
    asm("cvt.rna.tf32.f32 %0, %1;" : "=r"(y) : "f"(x));
    return __uint_as_float(y);
}

__device__ __forceinline__ void mma_tf32_16x8x8(
    float& c0, float& c1, float& c2, float& c3,
    uint32_t a0, uint32_t a1, uint32_t a2, uint32_t a3,
    uint32_t b0, uint32_t b1)
{
    asm volatile(
        "mma.sync.aligned.m16n8k8.row.col.f32.tf32.tf32.f32 "
        "{%0,%1,%2,%3}, {%4,%5,%6,%7}, {%8,%9}, {%0,%1,%2,%3};\n"
        : "+f"(c0), "+f"(c1), "+f"(c2), "+f"(c3)
        : "r"(a0), "r"(a1), "r"(a2), "r"(a3), "r"(b0), "r"(b1));
}

__device__ __forceinline__ uint32_t smem_u32(const void* p) {
    uint32_t a;
    asm("{ .reg .u64 t; cvta.to.shared.u64 t, %1; cvt.u32.u64 %0, t; }"
        : "=r"(a) : "l"(p));
    return a;
}

#define CP_ASYNC16(dst, src) \
    asm volatile("cp.async.cg.shared.global [%0], [%1], 16;" \
                 :: "r"(dst), "l"(src) : "memory")
#define CP_COMMIT() asm volatile("cp.async.commit_group;" ::: "memory")
#define CP_WAIT(n)  asm volatile("cp.async.wait_group %0;" :: "n"(n) : "memory")

// ---------------------------------------------------------------------------
// Projection GEMM (R8 double-buffered legacy-tf32), with epilogue control:
// out = (acc + bias) * oscale; if (oround) out = tf32(out).
// ---------------------------------------------------------------------------
__global__ __launch_bounds__(256) void gemm_tf32_nt_bias(
    const float* __restrict__ A, const float* __restrict__ W,
    const float* __restrict__ bias, float* __restrict__ C,
    int M, int N, int K, float oscale, int oround)
{
    extern __shared__ float gsm[];
    float* As = gsm;                    // [2][128][36]
    float* Bs = gsm + 2 * 128 * 36;     // [2][128][36]

    const int tid  = threadIdx.x;
    const int wid  = tid >> 5;
    const int lane = tid & 31;
    const int g    = lane >> 2;
    const int tig  = lane & 3;
    const int warp_m = (wid >> 2) * 64;
    const int warp_n = (wid & 3) * 32;
    const int bm = blockIdx.y * 128;
    const int bn = blockIdx.x * 128;

    const int lrow = tid >> 3;
    const int lcol = (tid & 7) * 4;

    float acc[4][4][4];
#pragma unroll
    for (int mf = 0; mf < 4; mf++)
#pragma unroll
        for (int nf = 0; nf < 4; nf++)
#pragma unroll
            for (int r = 0; r < 4; r++) acc[mf][nf][r] = 0.f;

    const float* aptr = A + (size_t)(bm + lrow) * K + lcol;
    const float* bptr = W + (size_t)(bn + lrow) * K + lcol;

    float4 ra[4], rb[4];
#pragma unroll
    for (int u = 0; u < 4; u++) {
        ra[u] = *(const float4*)(aptr + (size_t)u * 32 * K);
        rb[u] = *(const float4*)(bptr + (size_t)u * 32 * K);
    }
#pragma unroll
    for (int u = 0; u < 4; u++) {
        int r = lrow + u * 32;
        float* ad = &As[r * 36 + lcol];
        float* bd = &Bs[r * 36 + lcol];
        ad[0] = to_tf32(ra[u].x); ad[1] = to_tf32(ra[u].y);
        ad[2] = to_tf32(ra[u].z); ad[3] = to_tf32(ra[u].w);
        bd[0] = to_tf32(rb[u].x); bd[1] = to_tf32(rb[u].y);
        bd[2] = to_tf32(rb[u].z); bd[3] = to_tf32(rb[u].w);
    }
    __syncthreads();

    const int kTiles = K >> 5;
    for (int kt = 0; kt < kTiles; kt++) {
        const int cur = (kt & 1) * 128 * 36;
        const int nxt = ((kt + 1) & 1) * 128 * 36;
        const bool pf = (kt + 1 < kTiles);
        if (pf) {
            const float* ap = aptr + (size_t)(kt + 1) * 32;
            const float* bp = bptr + (size_t)(kt + 1) * 32;
#pragma unroll
            for (int u = 0; u < 4; u++) {
                ra[u] = *(const float4*)(ap + (size_t)u * 32 * K);
                rb[u] = *(const float4*)(bp + (size_t)u * 32 * K);
            }
        }
#pragma unroll
        for (int ks = 0; ks < 4; ks++) {
            const int k0 = ks * 8;
            uint32_t af[4][4];
#pragma unroll
            for (int mf = 0; mf < 4; mf++) {
                int row = warp_m + mf * 16;
                af[mf][0] = __float_as_uint(As[cur + (row + g    ) * 36 + k0 + tig    ]);
                af[mf][1] = __float_as_uint(As[cur + (row + g + 8) * 36 + k0 + tig    ]);
                af[mf][2] = __float_as_uint(As[cur + (row + g    ) * 36 + k0 + tig + 4]);
                af[mf][3] = __float_as_uint(As[cur + (row + g + 8) * 36 + k0 + tig + 4]);
            }
            uint32_t bf[4][2];
#pragma unroll
            for (int nf = 0; nf < 4; nf++) {
                int col = warp_n + nf * 8;
                bf[nf][0] = __float_as_uint(Bs[cur + (col + g) * 36 + k0 + tig    ]);
                bf[nf][1] = __float_as_uint(Bs[cur + (col + g) * 36 + k0 + tig + 4]);
            }
#pragma unroll
            for (int mf = 0; mf < 4; mf++)
#pragma unroll
                for (int nf = 0; nf < 4; nf++)
                    mma_tf32_16x8x8(acc[mf][nf][0], acc[mf][nf][1],
                                    acc[mf][nf][2], acc[mf][nf][3],
                                    af[mf][0], af[mf][1], af[mf][2], af[mf][3],
                                    bf[nf][0], bf[nf][1]);
        }
        if (pf) {
#pragma unroll
            for (int u = 0; u < 4; u++) {
                int r = lrow + u * 32;
                float* ad = &As[nxt + r * 36 + lcol];
                float* bd = &Bs[nxt + r * 36 + lcol];
                ad[0] = to_tf32(ra[u].x); ad[1] = to_tf32(ra[u].y);
                ad[2] = to_tf32(ra[u].z); ad[3] = to_tf32(ra[u].w);
                bd[0] = to_tf32(rb[u].x); bd[1] = to_tf32(rb[u].y);
                bd[2] = to_tf32(rb[u].z); bd[3] = to_tf32(rb[u].w);
            }
        }
        __syncthreads();
    }

#pragma unroll
    for (int mf = 0; mf < 4; mf++) {
        int row0 = bm + warp_m + mf * 16 + g;
#pragma unroll
        for (int nf = 0; nf < 4; nf++) {
            int col = bn + warp_n + nf * 8 + 2 * tig;
            float bv0 = bias[col], bv1 = bias[col + 1];
            float v00 = (acc[mf][nf][0] + bv0) * oscale;
            float v01 = (acc[mf][nf][1] + bv1) * oscale;
            float v10 = (acc[mf][nf][2] + bv0) * oscale;
            float v11 = (acc[mf][nf][3] + bv1) * oscale;
            if (oround) {
                v00 = to_tf32(v00); v01 = to_tf32(v01);
                v10 = to_tf32(v10); v11 = to_tf32(v11);
            }
            *(float2*)&C[(size_t)row0 * N + col]       = make_float2(v00, v01);
            *(float2*)&C[(size_t)(row0 + 8) * N + col] = make_float2(v10, v11);
        }
    }
}

// ---------------------------------------------------------------------------
// Stage one 64-row KV tile (+mask) into ring slot via cp.async (16B chunks).
// ---------------------------------------------------------------------------
__device__ __forceinline__ void stage_kv(
    uint32_t ks_u32, uint32_t vs_u32, uint32_t ms_u32, int slot,
    const float* kp, const float* vp, const unsigned char* mp,
    int sr, int sc, int tid)
{
#pragma unroll
    for (int u = 0; u < 4; u++) {
        int r = sr + u * 16;
        CP_ASYNC16(ks_u32 + (uint32_t)(slot * BKV * LDS_K + r * LDS_K + sc) * 4,
                   kp + (size_t)r * D_MODEL + sc);
        CP_ASYNC16(vs_u32 + (uint32_t)(slot * BKV * LDS_V + r * LDS_V + sc) * 4,
                   vp + (size_t)r * D_MODEL + sc);
    }
    if (tid < 4)
        CP_ASYNC16(ms_u32 + (uint32_t)(slot * BKV + tid * 16), mp + tid * 16);
}

// ---------------------------------------------------------------------------
// Tensor-core flash attention, cp.async 3-stage ring. Inputs pre-rounded tf32
// (q also pre-scaled). grid (TQ/128, B*H), 8 warps; warp w owns rows [16w,16w+16).
// ---------------------------------------------------------------------------
__global__ __launch_bounds__(256) void attn_tc_kernel(
    const float* __restrict__ qb, const float* __restrict__ kb,
    const float* __restrict__ vb, const unsigned char* __restrict__ mask,
    float* __restrict__ ctx)
{
    extern __shared__ float sm[];
    float* Ps = sm;                               // [128][LDS_P]
    float* Ks = Ps + BQ * LDS_P;                  // [3][64][LDS_K]
    float* Vs = Ks + STAGES * BKV * LDS_K;        // [3][64][LDS_V]
    unsigned char* Ms = (unsigned char*)(Vs + STAGES * BKV * LDS_V);  // [3][64]

    const int tid  = threadIdx.x;
    const int wid  = tid >> 5;
    const int lane = tid & 31;
    const int g    = lane >> 2;
    const int tig  = lane & 3;
    const int qr0  = wid * 16;
    const int b = blockIdx.y / NH;
    const int h = blockIdx.y % NH;
    const int t0 = blockIdx.x * BQ;

    const int sr = tid >> 4;
    const int sc = (tid & 15) * 4;

    const uint32_t ps_u32 = smem_u32(Ps);
    const uint32_t ks_u32 = smem_u32(Ks);
    const uint32_t vs_u32 = smem_u32(Vs);
    const uint32_t ms_u32 = smem_u32(Ms);

    const float* qbase = qb + ((size_t)b * TQ + t0) * D_MODEL + h * HDIM;
    const float* kbase = kb + ((size_t)b * NKV) * D_MODEL + h * HDIM;
    const float* vbase = vb + ((size_t)b * NKV) * D_MODEL + h * HDIM;
    const unsigned char* mbase = mask + (size_t)b * NKV;

    // group A: Q tile (already tf32 * SCALE)
#pragma unroll
    for (int u = 0; u < 8; u++) {
        int idx = tid + u * 256;
        int r = idx >> 4, c = (idx & 15) * 4;
        CP_ASYNC16(ps_u32 + (uint32_t)(r * LDS_P + c) * 4,
                   qbase + (size_t)r * D_MODEL + c);
    }
    CP_COMMIT();
    // groups s0, s1
    stage_kv(ks_u32, vs_u32, ms_u32, 0, kbase, vbase, mbase, sr, sc, tid);
    CP_COMMIT();
    stage_kv(ks_u32, vs_u32, ms_u32, 1, kbase + (size_t)BKV * D_MODEL,
             vbase + (size_t)BKV * D_MODEL, mbase + BKV, sr, sc, tid);
    CP_COMMIT();

    CP_WAIT(2);            // group A (Q) done
    __syncthreads();

    uint32_t qa[8][4];
#pragma unroll
    for (int ks = 0; ks < 8; ks++) {
        int k0 = ks * 8;
        qa[ks][0] = __float_as_uint(Ps[(qr0 + g    ) * LDS_P + k0 + tig    ]);
        qa[ks][1] = __float_as_uint(Ps[(qr0 + g + 8) * LDS_P + k0 + tig    ]);
        qa[ks][2] = __float_as_uint(Ps[(qr0 + g    ) * LDS_P + k0 + tig + 4]);
        qa[ks][3] = __float_as_uint(Ps[(qr0 + g + 8) * LDS_P + k0 + tig + 4]);
    }

    float m0 = -1e30f, m1 = -1e30f, l0 = 0.f, l1 = 0.f;
    float o[8][4];
#pragma unroll
    for (int df = 0; df < 8; df++)
#pragma unroll
        for (int r = 0; r < 4; r++) o[df][r] = 0.f;

    const int nTiles = NKV / BKV;      // 24
    int slot = 0;
    for (int t = 0; t < nTiles; t++, slot = (slot + 1 == STAGES ? 0 : slot + 1)) {
        CP_WAIT(1);                    // stage t arrived (this thread)
        __syncthreads();               // all threads' stages visible; t-1 done

        // issue stage t+2 into slot (t+2)%3 (== slot of t-1, now free)
        if (t + 2 < nTiles) {
            int ns = slot + 2 >= STAGES ? slot + 2 - STAGES : slot + 2;
            stage_kv(ks_u32, vs_u32, ms_u32, ns,
                     kbase + (size_t)(t + 2) * BKV * D_MODEL,
                     vbase + (size_t)(t + 2) * BKV * D_MODEL,
                     mbase + (t + 2) * BKV, sr, sc, tid);
        }
        CP_COMMIT();                   // always one group per iteration

        const int cK = slot * BKV * LDS_K;
        const int cV = slot * BKV * LDS_V;
        const int cM = slot * BKV;

        // ---- S = Q @ K^T ----
        float s[8][4];
#pragma unroll
        for (int nf = 0; nf < 8; nf++) {
            s[nf][0] = 0.f; s[nf][1] = 0.f; s[nf][2] = 0.f; s[nf][3] = 0.f;
#pragma unroll
            for (int ks = 0; ks < 8; ks++) {
                int k0 = ks * 8;
                uint32_t b0 = __float_as_uint(Ks[cK + (nf * 8 + g) * LDS_K + k0 + tig    ]);
                uint32_t b1 = __float_as_uint(Ks[cK + (nf * 8 + g) * LDS_K + k0 + tig + 4]);
                mma_tf32_16x8x8(s[nf][0], s[nf][1], s[nf][2], s[nf][3],
                                qa[ks][0], qa[ks][1], qa[ks][2], qa[ks][3], b0, b1);
            }
        }

        // ---- mask ----
#pragma unroll
        for (int nf = 0; nf < 8; nf++) {
            int c0 = cM + nf * 8 + 2 * tig;
            if (Ms[c0])     { s[nf][0] = -1e30f; s[nf][2] = -1e30f; }
            if (Ms[c0 + 1]) { s[nf][1] = -1e30f; s[nf][3] = -1e30f; }
        }

        // ---- warp-local online softmax ----
        float rmax0 = -1e30f, rmax1 = -1e30f;
#pragma unroll
        for (int nf = 0; nf < 8; nf++) {
            rmax0 = fmaxf(rmax0, fmaxf(s[nf][0], s[nf][1]));
            rmax1 = fmaxf(rmax1, fmaxf(s[nf][2], s[nf][3]));
        }
        rmax0 = fmaxf(rmax0, __shfl_xor_sync(0xffffffffu, rmax0, 1));
        rmax0 = fmaxf(rmax0, __shfl_xor_sync(0xffffffffu, rmax0, 2));
        rmax1 = fmaxf(rmax1, __shfl_xor_sync(0xffffffffu, rmax1, 1));
        rmax1 = fmaxf(rmax1, __shfl_xor_sync(0xffffffffu, rmax1, 2));

        float mn0 = fmaxf(m0, rmax0), mn1 = fmaxf(m1, rmax1);
        float corr0 = __expf(m0 - mn0), corr1 = __expf(m1 - mn1);
        m0 = mn0; m1 = mn1;

        float rs0 = 0.f, rs1 = 0.f;
#pragma unroll
        for (int nf = 0; nf < 8; nf++) {
            s[nf][0] = __expf(s[nf][0] - mn0); rs0 += s[nf][0];
            s[nf][1] = __expf(s[nf][1] - mn0); rs0 += s[nf][1];
            s[nf][2] = __expf(s[nf][2] - mn1); rs1 += s[nf][2];
            s[nf][3] = __expf(s[nf][3] - mn1); rs1 += s[nf][3];
        }
        rs0 += __shfl_xor_sync(0xffffffffu, rs0, 1);
        rs0 += __shfl_xor_sync(0xffffffffu, rs0, 2);
        rs1 += __shfl_xor_sync(0xffffffffu, rs1, 1);
        rs1 += __shfl_xor_sync(0xffffffffu, rs1, 2);
        l0 = l0 * corr0 + rs0;
        l1 = l1 * corr1 + rs1;

        // ---- P -> smem (warp-private rows) ----
#pragma unroll
        for (int nf = 0; nf < 8; nf++) {
            int col = nf * 8 + 2 * tig;
            *(float2*)&Ps[(qr0 + g    ) * LDS_P + col] =
                make_float2(to_tf32(s[nf][0]), to_tf32(s[nf][1]));
            *(float2*)&Ps[(qr0 + g + 8) * LDS_P + col] =
                make_float2(to_tf32(s[nf][2]), to_tf32(s[nf][3]));
        }
        __syncwarp();

        // ---- O = O*corr + P @ V ----
#pragma unroll
        for (int df = 0; df < 8; df++) {
            o[df][0] *= corr0; o[df][1] *= corr0;
            o[df][2] *= corr1; o[df][3] *= corr1;
        }
#pragma unroll
        for (int ks = 0; ks < 8; ks++) {
            int k0 = ks * 8;
            uint32_t pa0 = __float_as_uint(Ps[(qr0 + g    ) * LDS_P + k0 + tig    ]);
            uint32_t pa1 = __float_as_uint(Ps[(qr0 + g + 8) * LDS_P + k0 + tig    ]);
            uint32_t pa2 = __float_as_uint(Ps[(qr0 + g    ) * LDS_P + k0 + tig + 4]);
            uint32_t pa3 = __float_as_uint(Ps[(qr0 + g + 8) * LDS_P + k0 + tig + 4]);
#pragma unroll
            for (int df = 0; df < 8; df++) {
                uint32_t vb0 = __float_as_uint(Vs[cV + (k0 + tig    ) * LDS_V + df * 8 + g]);
                uint32_t vb1 = __float_as_uint(Vs[cV + (k0 + tig + 4) * LDS_V + df * 8 + g]);
                mma_tf32_16x8x8(o[df][0], o[df][1], o[df][2], o[df][3],
                                pa0, pa1, pa2, pa3, vb0, vb1);
            }
        }
    }

    // ---- normalize, write ----
    float inv0 = 1.f / l0, inv1 = 1.f / l1;
    float* obase = ctx + ((size_t)b * TQ + t0) * D_MODEL + h * HDIM;
#pragma unroll
    for (int df = 0; df < 8; df++) {
        int col = df * 8 + 2 * tig;
        *(float2*)&obase[(size_t)(qr0 + g    ) * D_MODEL + col] =
            make_float2(o[df][0] * inv0, o[df][1] * inv0);
        *(float2*)&obase[(size_t)(qr0 + g + 8) * D_MODEL + col] =
            make_float2(o[df][2] * inv1, o[df][3] * inv1);
    }
}

// ---------------------------------------------------------------------------
extern "C" void kernel_launch(void* const* d_in, const int* in_sizes, int n_in,
                              void* d_out, int out_size)
{
    const float* query = (const float*)d_in[0];
    const float* kv    = (const float*)d_in[1];
    const unsigned char* mask = (const unsigned char*)d_in[2];
    const float* Wq = (const float*)d_in[3];
    const float* bq = (const float*)d_in[4];
    const float* Wk = (const float*)d_in[5];
    const float* bk = (const float*)d_in[6];
    const float* Wv = (const float*)d_in[7];
    const float* bv = (const float*)d_in[8];
    const float* Wo = (const float*)d_in[9];
    const float* bo = (const float*)d_in[10];
    float* out = (float*)d_out;

    static float *qb = nullptr, *kb = nullptr, *vbuf = nullptr, *cb = nullptr;
    static const int SMEM_GEMM = 4 * 128 * 36 * 4;                        // 73728
    static const int SMEM_ATTN =
        (BQ * LDS_P + STAGES * BKV * LDS_K + STAGES * BKV * LDS_V) * 4
        + STAGES * BKV;                                                    // 142528
    if (!qb) {
        cudaGetSymbolAddress((void**)&qb,   g_q);
        cudaGetSymbolAddress((void**)&kb,   g_k);
        cudaGetSymbolAddress((void**)&vbuf, g_v);
        cudaGetSymbolAddress((void**)&cb,   g_ctx);
        cudaFuncSetAttribute(gemm_tf32_nt_bias,
                             cudaFuncAttributeMaxDynamicSharedMemorySize, SMEM_GEMM);
        cudaFuncSetAttribute(attn_tc_kernel,
                             cudaFuncAttributeMaxDynamicSharedMemorySize, SMEM_ATTN);
    }

    dim3 blk(256);
    // Projections; q/k/v outputs pre-rounded to tf32 (q pre-scaled too)
    gemm_tf32_nt_bias<<<dim3(8, 64), blk, SMEM_GEMM>>>(query, Wq, bq, qb,
        B_ * TQ,  D_MODEL, D_MODEL, SCALE, 1);
    gemm_tf32_nt_bias<<<dim3(8, 96), blk, SMEM_GEMM>>>(kv,    Wk, bk, kb,
        B_ * NKV, D_MODEL, D_MODEL, 1.0f, 1);
    gemm_tf32_nt_bias<<<dim3(8, 96), blk, SMEM_GEMM>>>(kv,    Wv, bv, vbuf,
        B_ * NKV, D_MODEL, D_MODEL, 1.0f, 1);

    attn_tc_kernel<<<dim3(TQ / BQ, B_ * NH), blk, SMEM_ATTN>>>(qb, kb, vbuf, mask, cb);

    // Output projection (plain fp32 epilogue)
    gemm_tf32_nt_bias<<<dim3(8, 64), blk, SMEM_GEMM>>>(cb, Wo, bo, out,
        B_ * TQ, D_MODEL, D_MODEL, 1.0f, 0);
}

// round 11
// speedup vs baseline: 3.7040x; 1.2031x over previous
#include <cuda_runtime.h>
#include <cstdint>

#define D_MODEL 1024
#define NH      16
#define HDIM    64
#define B_      8
#define TQ      1024
#define NKV     1536
#define SCALE   0.125f   // HD^-0.5 (exact power of two)

// attention tiles
#define BQ     128
#define BKV    64
#define LDS_P  68
#define LDS_K  68
#define LDS_V  72
#define STAGES 2

// Scratch (allocation-free rule: __device__ globals)
__device__ float g_q[B_ * TQ * D_MODEL];      // tf32(q_proj*SCALE)
__device__ float g_k[B_ * NKV * D_MODEL];     // tf32(k_proj)
__device__ float g_v[B_ * NKV * D_MODEL];     // tf32(v_proj)
__device__ float g_ctx[B_ * TQ * D_MODEL];    // tf32(attention out)
__device__ float g_qin[B_ * TQ * D_MODEL];    // tf32(query)
__device__ float g_kvin[B_ * NKV * D_MODEL];  // tf32(key_value)
__device__ float g_wq[D_MODEL * D_MODEL];     // tf32 weights
__device__ float g_wk[D_MODEL * D_MODEL];
__device__ float g_wv[D_MODEL * D_MODEL];
__device__ float g_wo[D_MODEL * D_MODEL];

// ---------------------------------------------------------------------------
__device__ __forceinline__ float to_tf32(float x) {
    uint32_t y;
    asm("cvt.rna.tf32.f32 %0, %1;" : "=r"(y) : "f"(x));
    return __uint_as_float(y);
}

__device__ __forceinline__ void mma_tf32_16x8x8(
    float& c0, float& c1, float& c2, float& c3,
    uint32_t a0, uint32_t a1, uint32_t a2, uint32_t a3,
    uint32_t b0, uint32_t b1)
{
    asm volatile(
        "mma.sync.aligned.m16n8k8.row.col.f32.tf32.tf32.f32 "
        "{%0,%1,%2,%3}, {%4,%5,%6,%7}, {%8,%9}, {%0,%1,%2,%3};\n"
        : "+f"(c0), "+f"(c1), "+f"(c2), "+f"(c3)
        : "r"(a0), "r"(a1), "r"(a2), "r"(a3), "r"(b0), "r"(b1));
}

__device__ __forceinline__ uint32_t smem_u32(const void* p) {
    uint32_t a;
    asm("{ .reg .u64 t; cvta.to.shared.u64 t, %1; cvt.u32.u64 %0, t; }"
        : "=r"(a) : "l"(p));
    return a;
}

#define CP_ASYNC16(dst, src) \
    asm volatile("cp.async.cg.shared.global [%0], [%1], 16;" \
                 :: "r"(dst), "l"(src) : "memory")
#define CP_COMMIT() asm volatile("cp.async.commit_group;" ::: "memory")
#define CP_WAIT(n)  asm volatile("cp.async.wait_group %0;" :: "n"(n) : "memory")

// ---------------------------------------------------------------------------
// Elementwise tf32 rounding (inputs pre-pass). n % 1024 == 0 for all uses.
// ---------------------------------------------------------------------------
__global__ __launch_bounds__(256) void cvt_tf32_kernel(
    const float* __restrict__ src, float* __restrict__ dst, int n)
{
    int i = (blockIdx.x * 256 + threadIdx.x) * 4;
    if (i < n) {
        float4 v = *(const float4*)(src + i);
        v.x = to_tf32(v.x); v.y = to_tf32(v.y);
        v.z = to_tf32(v.z); v.w = to_tf32(v.w);
        *(float4*)(dst + i) = v;
    }
}

// ---------------------------------------------------------------------------
// Projection GEMM: inputs are PRE-ROUNDED tf32; cp.async 2-stage ring, no cvt,
// 2 CTAs/SM. out = (acc + bias) * oscale; if (oround) out = tf32(out).
// ---------------------------------------------------------------------------
__global__ __launch_bounds__(256, 2) void gemm_tf32_nt_bias(
    const float* __restrict__ A, const float* __restrict__ W,
    const float* __restrict__ bias, float* __restrict__ C,
    int M, int N, int K, float oscale, int oround)
{
    extern __shared__ float gsm[];
    float* As = gsm;                    // [2][128][36]
    float* Bs = gsm + 2 * 128 * 36;     // [2][128][36]
    const uint32_t as_u32 = smem_u32(As);
    const uint32_t bs_u32 = smem_u32(Bs);

    const int tid  = threadIdx.x;
    const int wid  = tid >> 5;
    const int lane = tid & 31;
    const int g    = lane >> 2;
    const int tig  = lane & 3;
    const int warp_m = (wid >> 2) * 64;
    const int warp_n = (wid & 3) * 32;
    const int bm = blockIdx.y * 128;
    const int bn = blockIdx.x * 128;

    const int crow = tid >> 3;          // 0..31 (+32u)
    const int ccol = (tid & 7) * 4;     // 0..28 (float col)

    const float* aptr = A + (size_t)(bm + crow) * K + ccol;
    const float* bptr = W + (size_t)(bn + crow) * K + ccol;

    float acc[4][4][4];
#pragma unroll
    for (int mf = 0; mf < 4; mf++)
#pragma unroll
        for (int nf = 0; nf < 4; nf++)
#pragma unroll
            for (int r = 0; r < 4; r++) acc[mf][nf][r] = 0.f;

    // prologue: tile 0 -> slot 0
#pragma unroll
    for (int u = 0; u < 4; u++) {
        int r = crow + u * 32;
        CP_ASYNC16(as_u32 + (uint32_t)(r * 36 + ccol) * 4,
                   aptr + (size_t)u * 32 * K);
        CP_ASYNC16(bs_u32 + (uint32_t)(r * 36 + ccol) * 4,
                   bptr + (size_t)u * 32 * K);
    }
    CP_COMMIT();

    const int kTiles = K >> 5;
    for (int kt = 0; kt < kTiles; kt++) {
        const int cur = (kt & 1) * 128 * 36;
        const int nxt = ((kt + 1) & 1) * 128 * 36;
        CP_WAIT(0);
        __syncthreads();
        if (kt + 1 < kTiles) {
            const float* ap = aptr + (size_t)(kt + 1) * 32;
            const float* bp = bptr + (size_t)(kt + 1) * 32;
#pragma unroll
            for (int u = 0; u < 4; u++) {
                int r = crow + u * 32;
                CP_ASYNC16(as_u32 + (uint32_t)(nxt + r * 36 + ccol) * 4,
                           ap + (size_t)u * 32 * K);
                CP_ASYNC16(bs_u32 + (uint32_t)(nxt + r * 36 + ccol) * 4,
                           bp + (size_t)u * 32 * K);
            }
        }
        CP_COMMIT();
#pragma unroll
        for (int ks = 0; ks < 4; ks++) {
            const int k0 = ks * 8;
            uint32_t af[4][4];
#pragma unroll
            for (int mf = 0; mf < 4; mf++) {
                int row = warp_m + mf * 16;
                af[mf][0] = __float_as_uint(As[cur + (row + g    ) * 36 + k0 + tig    ]);
                af[mf][1] = __float_as_uint(As[cur + (row + g + 8) * 36 + k0 + tig    ]);
                af[mf][2] = __float_as_uint(As[cur + (row + g    ) * 36 + k0 + tig + 4]);
                af[mf][3] = __float_as_uint(As[cur + (row + g + 8) * 36 + k0 + tig + 4]);
            }
            uint32_t bf[4][2];
#pragma unroll
            for (int nf = 0; nf < 4; nf++) {
                int col = warp_n + nf * 8;
                bf[nf][0] = __float_as_uint(Bs[cur + (col + g) * 36 + k0 + tig    ]);
                bf[nf][1] = __float_as_uint(Bs[cur + (col + g) * 36 + k0 + tig + 4]);
            }
#pragma unroll
            for (int mf = 0; mf < 4; mf++)
#pragma unroll
                for (int nf = 0; nf < 4; nf++)
                    mma_tf32_16x8x8(acc[mf][nf][0], acc[mf][nf][1],
                                    acc[mf][nf][2], acc[mf][nf][3],
                                    af[mf][0], af[mf][1], af[mf][2], af[mf][3],
                                    bf[nf][0], bf[nf][1]);
        }
    }

#pragma unroll
    for (int mf = 0; mf < 4; mf++) {
        int row0 = bm + warp_m + mf * 16 + g;
#pragma unroll
        for (int nf = 0; nf < 4; nf++) {
            int col = bn + warp_n + nf * 8 + 2 * tig;
            float bv0 = bias[col], bv1 = bias[col + 1];
            float v00 = (acc[mf][nf][0] + bv0) * oscale;
            float v01 = (acc[mf][nf][1] + bv1) * oscale;
            float v10 = (acc[mf][nf][2] + bv0) * oscale;
            float v11 = (acc[mf][nf][3] + bv1) * oscale;
            if (oround) {
                v00 = to_tf32(v00); v01 = to_tf32(v01);
                v10 = to_tf32(v10); v11 = to_tf32(v11);
            }
            *(float2*)&C[(size_t)row0 * N + col]       = make_float2(v00, v01);
            *(float2*)&C[(size_t)(row0 + 8) * N + col] = make_float2(v10, v11);
        }
    }
}

// ---------------------------------------------------------------------------
__device__ __forceinline__ void stage_kv(
    uint32_t ks_u32, uint32_t vs_u32, uint32_t ms_u32, int slot,
    const float* kp, const float* vp, const unsigned char* mp,
    int sr, int sc, int tid)
{
#pragma unroll
    for (int u = 0; u < 4; u++) {
        int r = sr + u * 16;
        CP_ASYNC16(ks_u32 + (uint32_t)(slot * BKV * LDS_K + r * LDS_K + sc) * 4,
                   kp + (size_t)r * D_MODEL + sc);
        CP_ASYNC16(vs_u32 + (uint32_t)(slot * BKV * LDS_V + r * LDS_V + sc) * 4,
                   vp + (size_t)r * D_MODEL + sc);
    }
    if (tid < 4)
        CP_ASYNC16(ms_u32 + (uint32_t)(slot * BKV + tid * 16), mp + tid * 16);
}

// ---------------------------------------------------------------------------
// Tensor-core flash attention, cp.async 2-stage ring, 2 CTAs/SM.
// Inputs pre-rounded tf32 (q pre-scaled). Epilogue writes tf32 (feeds O-proj).
// ---------------------------------------------------------------------------
__global__ __launch_bounds__(256, 2) void attn_tc_kernel(
    const float* __restrict__ qb, const float* __restrict__ kb,
    const float* __restrict__ vb, const unsigned char* __restrict__ mask,
    float* __restrict__ ctx)
{
    extern __shared__ float sm[];
    float* Ps = sm;                               // [128][LDS_P]
    float* Ks = Ps + BQ * LDS_P;                  // [2][64][LDS_K]
    float* Vs = Ks + STAGES * BKV * LDS_K;        // [2][64][LDS_V]
    unsigned char* Ms = (unsigned char*)(Vs + STAGES * BKV * LDS_V);  // [2][64]

    const int tid  = threadIdx.x;
    const int wid  = tid >> 5;
    const int lane = tid & 31;
    const int g    = lane >> 2;
    const int tig  = lane & 3;
    const int qr0  = wid * 16;
    const int b = blockIdx.y / NH;
    const int h = blockIdx.y % NH;
    const int t0 = blockIdx.x * BQ;

    const int sr = tid >> 4;
    const int sc = (tid & 15) * 4;

    const uint32_t ps_u32 = smem_u32(Ps);
    const uint32_t ks_u32 = smem_u32(Ks);
    const uint32_t vs_u32 = smem_u32(Vs);
    const uint32_t ms_u32 = smem_u32(Ms);

    const float* qbase = qb + ((size_t)b * TQ + t0) * D_MODEL + h * HDIM;
    const float* kbase = kb + ((size_t)b * NKV) * D_MODEL + h * HDIM;
    const float* vbase = vb + ((size_t)b * NKV) * D_MODEL + h * HDIM;
    const unsigned char* mbase = mask + (size_t)b * NKV;

    // group A: Q tile
#pragma unroll
    for (int u = 0; u < 8; u++) {
        int idx = tid + u * 256;
        int r = idx >> 4, c = (idx & 15) * 4;
        CP_ASYNC16(ps_u32 + (uint32_t)(r * LDS_P + c) * 4,
                   qbase + (size_t)r * D_MODEL + c);
    }
    CP_COMMIT();
    // group s0
    stage_kv(ks_u32, vs_u32, ms_u32, 0, kbase, vbase, mbase, sr, sc, tid);
    CP_COMMIT();

    CP_WAIT(1);            // Q arrived
    __syncthreads();

    uint32_t qa[8][4];
#pragma unroll
    for (int ks = 0; ks < 8; ks++) {
        int k0 = ks * 8;
        qa[ks][0] = __float_as_uint(Ps[(qr0 + g    ) * LDS_P + k0 + tig    ]);
        qa[ks][1] = __float_as_uint(Ps[(qr0 + g + 8) * LDS_P + k0 + tig    ]);
        qa[ks][2] = __float_as_uint(Ps[(qr0 + g    ) * LDS_P + k0 + tig + 4]);
        qa[ks][3] = __float_as_uint(Ps[(qr0 + g + 8) * LDS_P + k0 + tig + 4]);
    }

    float m0 = -1e30f, m1 = -1e30f, l0 = 0.f, l1 = 0.f;
    float o[8][4];
#pragma unroll
    for (int df = 0; df < 8; df++)
#pragma unroll
        for (int r = 0; r < 4; r++) o[df][r] = 0.f;

    const int nTiles = NKV / BKV;      // 24
    for (int t = 0; t < nTiles; t++) {
        const int slot = t & 1;
        CP_WAIT(0);                    // stage t arrived
        __syncthreads();               // all threads past compute t-1

        if (t + 1 < nTiles) {
            stage_kv(ks_u32, vs_u32, ms_u32, 1 - slot,
                     kbase + (size_t)(t + 1) * BKV * D_MODEL,
                     vbase + (size_t)(t + 1) * BKV * D_MODEL,
                     mbase + (t + 1) * BKV, sr, sc, tid);
        }
        CP_COMMIT();

        const int cK = slot * BKV * LDS_K;
        const int cV = slot * BKV * LDS_V;
        const int cM = slot * BKV;

        // ---- S = Q @ K^T ----
        float s[8][4];
#pragma unroll
        for (int nf = 0; nf < 8; nf++) {
            s[nf][0] = 0.f; s[nf][1] = 0.f; s[nf][2] = 0.f; s[nf][3] = 0.f;
#pragma unroll
            for (int ks = 0; ks < 8; ks++) {
                int k0 = ks * 8;
                uint32_t b0 = __float_as_uint(Ks[cK + (nf * 8 + g) * LDS_K + k0 + tig    ]);
                uint32_t b1 = __float_as_uint(Ks[cK + (nf * 8 + g) * LDS_K + k0 + tig + 4]);
                mma_tf32_16x8x8(s[nf][0], s[nf][1], s[nf][2], s[nf][3],
                                qa[ks][0], qa[ks][1], qa[ks][2], qa[ks][3], b0, b1);
            }
        }

        // ---- mask ----
#pragma unroll
        for (int nf = 0; nf < 8; nf++) {
            int c0 = cM + nf * 8 + 2 * tig;
            if (Ms[c0])     { s[nf][0] = -1e30f; s[nf][2] = -1e30f; }
            if (Ms[c0 + 1]) { s[nf][1] = -1e30f; s[nf][3] = -1e30f; }
        }

        // ---- warp-local online softmax ----
        float rmax0 = -1e30f, rmax1 = -1e30f;
#pragma unroll
        for (int nf = 0; nf < 8; nf++) {
            rmax0 = fmaxf(rmax0, fmaxf(s[nf][0], s[nf][1]));
            rmax1 = fmaxf(rmax1, fmaxf(s[nf][2], s[nf][3]));
        }
        rmax0 = fmaxf(rmax0, __shfl_xor_sync(0xffffffffu, rmax0, 1));
        rmax0 = fmaxf(rmax0, __shfl_xor_sync(0xffffffffu, rmax0, 2));
        rmax1 = fmaxf(rmax1, __shfl_xor_sync(0xffffffffu, rmax1, 1));
        rmax1 = fmaxf(rmax1, __shfl_xor_sync(0xffffffffu, rmax1, 2));

        float mn0 = fmaxf(m0, rmax0), mn1 = fmaxf(m1, rmax1);
        float corr0 = __expf(m0 - mn0), corr1 = __expf(m1 - mn1);
        m0 = mn0; m1 = mn1;

        float rs0 = 0.f, rs1 = 0.f;
#pragma unroll
        for (int nf = 0; nf < 8; nf++) {
            s[nf][0] = __expf(s[nf][0] - mn0); rs0 += s[nf][0];
            s[nf][1] = __expf(s[nf][1] - mn0); rs0 += s[nf][1];
            s[nf][2] = __expf(s[nf][2] - mn1); rs1 += s[nf][2];
            s[nf][3] = __expf(s[nf][3] - mn1); rs1 += s[nf][3];
        }
        rs0 += __shfl_xor_sync(0xffffffffu, rs0, 1);
        rs0 += __shfl_xor_sync(0xffffffffu, rs0, 2);
        rs1 += __shfl_xor_sync(0xffffffffu, rs1, 1);
        rs1 += __shfl_xor_sync(0xffffffffu, rs1, 2);
        l0 = l0 * corr0 + rs0;
        l1 = l1 * corr1 + rs1;

        // ---- P -> smem (warp-private rows) ----
#pragma unroll
        for (int nf = 0; nf < 8; nf++) {
            int col = nf * 8 + 2 * tig;
            *(float2*)&Ps[(qr0 + g    ) * LDS_P + col] =
                make_float2(to_tf32(s[nf][0]), to_tf32(s[nf][1]));
            *(float2*)&Ps[(qr0 + g + 8) * LDS_P + col] =
                make_float2(to_tf32(s[nf][2]), to_tf32(s[nf][3]));
        }
        __syncwarp();

        // ---- O = O*corr + P @ V ----
#pragma unroll
        for (int df = 0; df < 8; df++) {
            o[df][0] *= corr0; o[df][1] *= corr0;
            o[df][2] *= corr1; o[df][3] *= corr1;
        }
#pragma unroll
        for (int ks = 0; ks < 8; ks++) {
            int k0 = ks * 8;
            uint32_t pa0 = __float_as_uint(Ps[(qr0 + g    ) * LDS_P + k0 + tig    ]);
            uint32_t pa1 = __float_as_uint(Ps[(qr0 + g + 8) * LDS_P + k0 + tig    ]);
            uint32_t pa2 = __float_as_uint(Ps[(qr0 + g    ) * LDS_P + k0 + tig + 4]);
            uint32_t pa3 = __float_as_uint(Ps[(qr0 + g + 8) * LDS_P + k0 + tig + 4]);
#pragma unroll
            for (int df = 0; df < 8; df++) {
                uint32_t vb0 = __float_as_uint(Vs[cV + (k0 + tig    ) * LDS_V + df * 8 + g]);
                uint32_t vb1 = __float_as_uint(Vs[cV + (k0 + tig + 4) * LDS_V + df * 8 + g]);
                mma_tf32_16x8x8(o[df][0], o[df][1], o[df][2], o[df][3],
                                pa0, pa1, pa2, pa3, vb0, vb1);
            }
        }
    }

    // ---- normalize, round to tf32 (O-proj input), write ----
    float inv0 = 1.f / l0, inv1 = 1.f / l1;
    float* obase = ctx + ((size_t)b * TQ + t0) * D_MODEL + h * HDIM;
#pragma unroll
    for (int df = 0; df < 8; df++) {
        int col = df * 8 + 2 * tig;
        *(float2*)&obase[(size_t)(qr0 + g    ) * D_MODEL + col] =
            make_float2(to_tf32(o[df][0] * inv0), to_tf32(o[df][1] * inv0));
        *(float2*)&obase[(size_t)(qr0 + g + 8) * D_MODEL + col] =
            make_float2(to_tf32(o[df][2] * inv1), to_tf32(o[df][3] * inv1));
    }
}

// ---------------------------------------------------------------------------
extern "C" void kernel_launch(void* const* d_in, const int* in_sizes, int n_in,
                              void* d_out, int out_size)
{
    const float* query = (const float*)d_in[0];
    const float* kv    = (const float*)d_in[1];
    const unsigned char* mask = (const unsigned char*)d_in[2];
    const float* Wq = (const float*)d_in[3];
    const float* bq = (const float*)d_in[4];
    const float* Wk = (const float*)d_in[5];
    const float* bk = (const float*)d_in[6];
    const float* Wv = (const float*)d_in[7];
    const float* bv = (const float*)d_in[8];
    const float* Wo = (const float*)d_in[9];
    const float* bo = (const float*)d_in[10];
    float* out = (float*)d_out;

    static float *qb = nullptr, *kb = nullptr, *vbuf = nullptr, *cb = nullptr;
    static float *qin = nullptr, *kvin = nullptr;
    static float *wq = nullptr, *wk = nullptr, *wv = nullptr, *wo = nullptr;
    static const int SMEM_GEMM = 4 * 128 * 36 * 4;                        // 73728
    static const int SMEM_ATTN =
        (BQ * LDS_P + STAGES * BKV * LDS_K + STAGES * BKV * LDS_V) * 4
        + STAGES * BKV;                                                    // 106624
    if (!qb) {
        cudaGetSymbolAddress((void**)&qb,   g_q);
        cudaGetSymbolAddress((void**)&kb,   g_k);
        cudaGetSymbolAddress((void**)&vbuf, g_v);
        cudaGetSymbolAddress((void**)&cb,   g_ctx);
        cudaGetSymbolAddress((void**)&qin,  g_qin);
        cudaGetSymbolAddress((void**)&kvin, g_kvin);
        cudaGetSymbolAddress((void**)&wq,   g_wq);
        cudaGetSymbolAddress((void**)&wk,   g_wk);
        cudaGetSymbolAddress((void**)&wv,   g_wv);
        cudaGetSymbolAddress((void**)&wo,   g_wo);
        cudaFuncSetAttribute(gemm_tf32_nt_bias,
                             cudaFuncAttributeMaxDynamicSharedMemorySize, SMEM_GEMM);
        cudaFuncSetAttribute(attn_tc_kernel,
                             cudaFuncAttributeMaxDynamicSharedMemorySize, SMEM_ATTN);
    }

    dim3 blk(256);
    // Pre-round all GEMM inputs to tf32 (numerics identical to cvt-at-STS)
    const int NQ = B_ * TQ * D_MODEL, NKVE = B_ * NKV * D_MODEL, NW = D_MODEL * D_MODEL;
    cvt_tf32_kernel<<<NQ   / 1024, blk>>>(query, qin,  NQ);
    cvt_tf32_kernel<<<NKVE / 1024, blk>>>(kv,    kvin, NKVE);
    cvt_tf32_kernel<<<NW   / 1024, blk>>>(Wq, wq, NW);
    cvt_tf32_kernel<<<NW   / 1024, blk>>>(Wk, wk, NW);
    cvt_tf32_kernel<<<NW   / 1024, blk>>>(Wv, wv, NW);
    cvt_tf32_kernel<<<NW   / 1024, blk>>>(Wo, wo, NW);

    // Projections; q/k/v outputs rounded tf32 (q pre-scaled)
    gemm_tf32_nt_bias<<<dim3(8, 64), blk, SMEM_GEMM>>>(qin,  wq, bq, qb,
        B_ * TQ,  D_MODEL, D_MODEL, SCALE, 1);
    gemm_tf32_nt_bias<<<dim3(8, 96), blk, SMEM_GEMM>>>(kvin, wk, bk, kb,
        B_ * NKV, D_MODEL, D_MODEL, 1.0f, 1);
    gemm_tf32_nt_bias<<<dim3(8, 96), blk, SMEM_GEMM>>>(kvin, wv, bv, vbuf,
        B_ * NKV, D_MODEL, D_MODEL, 1.0f, 1);

    attn_tc_kernel<<<dim3(TQ / BQ, B_ * NH), blk, SMEM_ATTN>>>(qb, kb, vbuf, mask, cb);

    // Output projection (ctx already tf32-rounded), fp32 epilogue
    gemm_tf32_nt_bias<<<dim3(8, 64), blk, SMEM_GEMM>>>(cb, wo, bo, out,
        B_ * TQ, D_MODEL, D_MODEL, 1.0f, 0);
}

// round 12
// speedup vs baseline: 3.9583x; 1.0687x over previous
#include <cuda_runtime.h>
#include <cstdint>

#define D_MODEL 1024
#define NH      16
#define HDIM    64
#define B_      8
#define TQ      1024
#define NKV     1536
#define SCALE   0.125f   // HD^-0.5 (exact power of two)

// attention tiles
#define BQ     128
#define BKV    64
#define LDS_P  68
#define LDS_K  68
#define LDS_V  72
#define STAGES 2

// Scratch (allocation-free rule: __device__ globals)
__device__ float g_q[B_ * TQ * D_MODEL];      // tf32(q_proj*SCALE)
__device__ float g_k[B_ * NKV * D_MODEL];     // tf32(k_proj)
__device__ float g_v[B_ * NKV * D_MODEL];     // tf32(v_proj)
__device__ float g_ctx[B_ * TQ * D_MODEL];    // tf32(attention out)
__device__ float g_qin[B_ * TQ * D_MODEL];    // tf32(query)
__device__ float g_kvin[B_ * NKV * D_MODEL];  // tf32(key_value)
__device__ float g_wq[D_MODEL * D_MODEL];     // tf32 weights
__device__ float g_wk[D_MODEL * D_MODEL];
__device__ float g_wv[D_MODEL * D_MODEL];
__device__ float g_wo[D_MODEL * D_MODEL];

// ---------------------------------------------------------------------------
__device__ __forceinline__ float to_tf32(float x) {
    uint32_t y;
    asm("cvt.rna.tf32.f32 %0, %1;" : "=r"(y) : "f"(x));
    return __uint_as_float(y);
}

__device__ __forceinline__ void mma_tf32_16x8x8(
    float& c0, float& c1, float& c2, float& c3,
    uint32_t a0, uint32_t a1, uint32_t a2, uint32_t a3,
    uint32_t b0, uint32_t b1)
{
    asm volatile(
        "mma.sync.aligned.m16n8k8.row.col.f32.tf32.tf32.f32 "
        "{%0,%1,%2,%3}, {%4,%5,%6,%7}, {%8,%9}, {%0,%1,%2,%3};\n"
        : "+f"(c0), "+f"(c1), "+f"(c2), "+f"(c3)
        : "r"(a0), "r"(a1), "r"(a2), "r"(a3), "r"(b0), "r"(b1));
}

__device__ __forceinline__ uint32_t smem_u32(const void* p) {
    uint32_t a;
    asm("{ .reg .u64 t; cvta.to.shared.u64 t, %1; cvt.u32.u64 %0, t; }"
        : "=r"(a) : "l"(p));
    return a;
}

#define CP_ASYNC16(dst, src) \
    asm volatile("cp.async.cg.shared.global [%0], [%1], 16;" \
                 :: "r"(dst), "l"(src) : "memory")
#define CP_COMMIT() asm volatile("cp.async.commit_group;" ::: "memory")
#define CP_WAIT(n)  asm volatile("cp.async.wait_group %0;" :: "n"(n) : "memory")

// ---------------------------------------------------------------------------
// Fused elementwise tf32 rounding over all 6 input arrays (one launch).
// ---------------------------------------------------------------------------
__global__ __launch_bounds__(256) void cvt_all_kernel(
    const float* __restrict__ query, float* __restrict__ qin,
    const float* __restrict__ kv,    float* __restrict__ kvin,
    const float* __restrict__ Wq, float* __restrict__ wq,
    const float* __restrict__ Wk, float* __restrict__ wk,
    const float* __restrict__ Wv, float* __restrict__ wv,
    const float* __restrict__ Wo, float* __restrict__ wo)
{
    const int NQ = B_ * TQ * D_MODEL;          // 8388608
    const int NKVE = B_ * NKV * D_MODEL;       // 12582912
    const int NW = D_MODEL * D_MODEL;          // 1048576
    int i = (blockIdx.x * 256 + threadIdx.x) * 4;
    const float* src; float* dst; int off;
    if (i < NQ)                       { src = query; dst = qin;  off = i; }
    else if (i < NQ + NKVE)           { src = kv;    dst = kvin; off = i - NQ; }
    else if (i < NQ + NKVE + NW)      { src = Wq; dst = wq; off = i - NQ - NKVE; }
    else if (i < NQ + NKVE + 2 * NW)  { src = Wk; dst = wk; off = i - NQ - NKVE - NW; }
    else if (i < NQ + NKVE + 3 * NW)  { src = Wv; dst = wv; off = i - NQ - NKVE - 2 * NW; }
    else                              { src = Wo; dst = wo; off = i - NQ - NKVE - 3 * NW; }
    float4 v = *(const float4*)(src + off);
    v.x = to_tf32(v.x); v.y = to_tf32(v.y);
    v.z = to_tf32(v.z); v.w = to_tf32(v.w);
    *(float4*)(dst + off) = v;
}

// ---------------------------------------------------------------------------
// GEMM body: C tile [bm:bm+128, bn:bn+128] = A @ W^T + bias (N=K=1024).
// Inputs pre-rounded tf32; cp.async 2-stage ring. Identical numerics to R11.
// ---------------------------------------------------------------------------
__device__ __forceinline__ void gemm_body(
    float* gsm,
    const float* __restrict__ A, const float* __restrict__ W,
    const float* __restrict__ bias, float* __restrict__ C,
    int bm, int bn, float oscale, int oround)
{
    const int N = D_MODEL, K = D_MODEL;
    float* As = gsm;                    // [2][128][36]
    float* Bs = gsm + 2 * 128 * 36;     // [2][128][36]
    const uint32_t as_u32 = smem_u32(As);
    const uint32_t bs_u32 = smem_u32(Bs);

    const int tid  = threadIdx.x;
    const int wid  = tid >> 5;
    const int lane = tid & 31;
    const int g    = lane >> 2;
    const int tig  = lane & 3;
    const int warp_m = (wid >> 2) * 64;
    const int warp_n = (wid & 3) * 32;

    const int crow = tid >> 3;
    const int ccol = (tid & 7) * 4;

    const float* aptr = A + (size_t)(bm + crow) * K + ccol;
    const float* bptr = W + (size_t)(bn + crow) * K + ccol;

    float acc[4][4][4];
#pragma unroll
    for (int mf = 0; mf < 4; mf++)
#pragma unroll
        for (int nf = 0; nf < 4; nf++)
#pragma unroll
            for (int r = 0; r < 4; r++) acc[mf][nf][r] = 0.f;

#pragma unroll
    for (int u = 0; u < 4; u++) {
        int r = crow + u * 32;
        CP_ASYNC16(as_u32 + (uint32_t)(r * 36 + ccol) * 4,
                   aptr + (size_t)u * 32 * K);
        CP_ASYNC16(bs_u32 + (uint32_t)(r * 36 + ccol) * 4,
                   bptr + (size_t)u * 32 * K);
    }
    CP_COMMIT();

    const int kTiles = K >> 5;
    for (int kt = 0; kt < kTiles; kt++) {
        const int cur = (kt & 1) * 128 * 36;
        const int nxt = ((kt + 1) & 1) * 128 * 36;
        CP_WAIT(0);
        __syncthreads();
        if (kt + 1 < kTiles) {
            const float* ap = aptr + (size_t)(kt + 1) * 32;
            const float* bp = bptr + (size_t)(kt + 1) * 32;
#pragma unroll
            for (int u = 0; u < 4; u++) {
                int r = crow + u * 32;
                CP_ASYNC16(as_u32 + (uint32_t)(nxt + r * 36 + ccol) * 4,
                           ap + (size_t)u * 32 * K);
                CP_ASYNC16(bs_u32 + (uint32_t)(nxt + r * 36 + ccol) * 4,
                           bp + (size_t)u * 32 * K);
            }
        }
        CP_COMMIT();
#pragma unroll
        for (int ks = 0; ks < 4; ks++) {
            const int k0 = ks * 8;
            uint32_t af[4][4];
#pragma unroll
            for (int mf = 0; mf < 4; mf++) {
                int row = warp_m + mf * 16;
                af[mf][0] = __float_as_uint(As[cur + (row + g    ) * 36 + k0 + tig    ]);
                af[mf][1] = __float_as_uint(As[cur + (row + g + 8) * 36 + k0 + tig    ]);
                af[mf][2] = __float_as_uint(As[cur + (row + g    ) * 36 + k0 + tig + 4]);
                af[mf][3] = __float_as_uint(As[cur + (row + g + 8) * 36 + k0 + tig + 4]);
            }
            uint32_t bf[4][2];
#pragma unroll
            for (int nf = 0; nf < 4; nf++) {
                int col = warp_n + nf * 8;
                bf[nf][0] = __float_as_uint(Bs[cur + (col + g) * 36 + k0 + tig    ]);
                bf[nf][1] = __float_as_uint(Bs[cur + (col + g) * 36 + k0 + tig + 4]);
            }
#pragma unroll
            for (int mf = 0; mf < 4; mf++)
#pragma unroll
                for (int nf = 0; nf < 4; nf++)
                    mma_tf32_16x8x8(acc[mf][nf][0], acc[mf][nf][1],
                                    acc[mf][nf][2], acc[mf][nf][3],
                                    af[mf][0], af[mf][1], af[mf][2], af[mf][3],
                                    bf[nf][0], bf[nf][1]);
        }
    }

#pragma unroll
    for (int mf = 0; mf < 4; mf++) {
        int row0 = bm + warp_m + mf * 16 + g;
#pragma unroll
        for (int nf = 0; nf < 4; nf++) {
            int col = bn + warp_n + nf * 8 + 2 * tig;
            float bv0 = bias[col], bv1 = bias[col + 1];
            float v00 = (acc[mf][nf][0] + bv0) * oscale;
            float v01 = (acc[mf][nf][1] + bv1) * oscale;
            float v10 = (acc[mf][nf][2] + bv0) * oscale;
            float v11 = (acc[mf][nf][3] + bv1) * oscale;
            if (oround) {
                v00 = to_tf32(v00); v01 = to_tf32(v01);
                v10 = to_tf32(v10); v11 = to_tf32(v11);
            }
            *(float2*)&C[(size_t)row0 * N + col]       = make_float2(v00, v01);
            *(float2*)&C[(size_t)(row0 + 8) * N + col] = make_float2(v10, v11);
        }
    }
}

// ---------------------------------------------------------------------------
// Fused Q/K/V projection launch: grid (8, 64+96+96). Job from blockIdx.y.
// ---------------------------------------------------------------------------
__global__ __launch_bounds__(256, 2) void gemm_qkv_fused(
    const float* __restrict__ qin, const float* __restrict__ kvin,
    const float* __restrict__ wq, const float* __restrict__ bq, float* __restrict__ qb,
    const float* __restrict__ wk, const float* __restrict__ bk, float* __restrict__ kb,
    const float* __restrict__ wv, const float* __restrict__ bv, float* __restrict__ vb)
{
    extern __shared__ float gsm[];
    const int y = blockIdx.y;
    const int bn = blockIdx.x * 128;
    if (y < 64) {
        gemm_body(gsm, qin, wq, bq, qb, y * 128, bn, SCALE, 1);
    } else if (y < 160) {
        gemm_body(gsm, kvin, wk, bk, kb, (y - 64) * 128, bn, 1.0f, 1);
    } else {
        gemm_body(gsm, kvin, wv, bv, vb, (y - 160) * 128, bn, 1.0f, 1);
    }
}

// O-projection (fp32 epilogue, ctx already tf32)
__global__ __launch_bounds__(256, 2) void gemm_o_proj(
    const float* __restrict__ cb, const float* __restrict__ wo,
    const float* __restrict__ bo, float* __restrict__ out)
{
    extern __shared__ float gsm[];
    gemm_body(gsm, cb, wo, bo, out, blockIdx.y * 128, blockIdx.x * 128, 1.0f, 0);
}

// ---------------------------------------------------------------------------
__device__ __forceinline__ void stage_kv(
    uint32_t ks_u32, uint32_t vs_u32, uint32_t ms_u32, int slot,
    const float* kp, const float* vp, const unsigned char* mp,
    int sr, int sc, int tid)
{
#pragma unroll
    for (int u = 0; u < 4; u++) {
        int r = sr + u * 16;
        CP_ASYNC16(ks_u32 + (uint32_t)(slot * BKV * LDS_K + r * LDS_K + sc) * 4,
                   kp + (size_t)r * D_MODEL + sc);
        CP_ASYNC16(vs_u32 + (uint32_t)(slot * BKV * LDS_V + r * LDS_V + sc) * 4,
                   vp + (size_t)r * D_MODEL + sc);
    }
    if (tid < 4)
        CP_ASYNC16(ms_u32 + (uint32_t)(slot * BKV + tid * 16), mp + tid * 16);
}

// ---------------------------------------------------------------------------
// Tensor-core flash attention (unchanged from R11): cp.async 2-stage ring,
// 2 CTAs/SM, tf32-rounded epilogue.
// ---------------------------------------------------------------------------
__global__ __launch_bounds__(256, 2) void attn_tc_kernel(
    const float* __restrict__ qb, const float* __restrict__ kb,
    const float* __restrict__ vb, const unsigned char* __restrict__ mask,
    float* __restrict__ ctx)
{
    extern __shared__ float sm[];
    float* Ps = sm;                               // [128][LDS_P]
    float* Ks = Ps + BQ * LDS_P;                  // [2][64][LDS_K]
    float* Vs = Ks + STAGES * BKV * LDS_K;        // [2][64][LDS_V]
    unsigned char* Ms = (unsigned char*)(Vs + STAGES * BKV * LDS_V);  // [2][64]

    const int tid  = threadIdx.x;
    const int wid  = tid >> 5;
    const int lane = tid & 31;
    const int g    = lane >> 2;
    const int tig  = lane & 3;
    const int qr0  = wid * 16;
    const int b = blockIdx.y / NH;
    const int h = blockIdx.y % NH;
    const int t0 = blockIdx.x * BQ;

    const int sr = tid >> 4;
    const int sc = (tid & 15) * 4;

    const uint32_t ps_u32 = smem_u32(Ps);
    const uint32_t ks_u32 = smem_u32(Ks);
    const uint32_t vs_u32 = smem_u32(Vs);
    const uint32_t ms_u32 = smem_u32(Ms);

    const float* qbase = qb + ((size_t)b * TQ + t0) * D_MODEL + h * HDIM;
    const float* kbase = kb + ((size_t)b * NKV) * D_MODEL + h * HDIM;
    const float* vbase = vb + ((size_t)b * NKV) * D_MODEL + h * HDIM;
    const unsigned char* mbase = mask + (size_t)b * NKV;

#pragma unroll
    for (int u = 0; u < 8; u++) {
        int idx = tid + u * 256;
        int r = idx >> 4, c = (idx & 15) * 4;
        CP_ASYNC16(ps_u32 + (uint32_t)(r * LDS_P + c) * 4,
                   qbase + (size_t)r * D_MODEL + c);
    }
    CP_COMMIT();
    stage_kv(ks_u32, vs_u32, ms_u32, 0, kbase, vbase, mbase, sr, sc, tid);
    CP_COMMIT();

    CP_WAIT(1);
    __syncthreads();

    uint32_t qa[8][4];
#pragma unroll
    for (int ks = 0; ks < 8; ks++) {
        int k0 = ks * 8;
        qa[ks][0] = __float_as_uint(Ps[(qr0 + g    ) * LDS_P + k0 + tig    ]);
        qa[ks][1] = __float_as_uint(Ps[(qr0 + g + 8) * LDS_P + k0 + tig    ]);
        qa[ks][2] = __float_as_uint(Ps[(qr0 + g    ) * LDS_P + k0 + tig + 4]);
        qa[ks][3] = __float_as_uint(Ps[(qr0 + g + 8) * LDS_P + k0 + tig + 4]);
    }

    float m0 = -1e30f, m1 = -1e30f, l0 = 0.f, l1 = 0.f;
    float o[8][4];
#pragma unroll
    for (int df = 0; df < 8; df++)
#pragma unroll
        for (int r = 0; r < 4; r++) o[df][r] = 0.f;

    const int nTiles = NKV / BKV;      // 24
    for (int t = 0; t < nTiles; t++) {
        const int slot = t & 1;
        CP_WAIT(0);
        __syncthreads();

        if (t + 1 < nTiles) {
            stage_kv(ks_u32, vs_u32, ms_u32, 1 - slot,
                     kbase + (size_t)(t + 1) * BKV * D_MODEL,
                     vbase + (size_t)(t + 1) * BKV * D_MODEL,
                     mbase + (t + 1) * BKV, sr, sc, tid);
        }
        CP_COMMIT();

        const int cK = slot * BKV * LDS_K;
        const int cV = slot * BKV * LDS_V;
        const int cM = slot * BKV;

        float s[8][4];
#pragma unroll
        for (int nf = 0; nf < 8; nf++) {
            s[nf][0] = 0.f; s[nf][1] = 0.f; s[nf][2] = 0.f; s[nf][3] = 0.f;
#pragma unroll
            for (int ks = 0; ks < 8; ks++) {
                int k0 = ks * 8;
                uint32_t b0 = __float_as_uint(Ks[cK + (nf * 8 + g) * LDS_K + k0 + tig    ]);
                uint32_t b1 = __float_as_uint(Ks[cK + (nf * 8 + g) * LDS_K + k0 + tig + 4]);
                mma_tf32_16x8x8(s[nf][0], s[nf][1], s[nf][2], s[nf][3],
                                qa[ks][0], qa[ks][1], qa[ks][2], qa[ks][3], b0, b1);
            }
        }

#pragma unroll
        for (int nf = 0; nf < 8; nf++) {
            int c0 = cM + nf * 8 + 2 * tig;
            if (Ms[c0])     { s[nf][0] = -1e30f; s[nf][2] = -1e30f; }
            if (Ms[c0 + 1]) { s[nf][1] = -1e30f; s[nf][3] = -1e30f; }
        }

        float rmax0 = -1e30f, rmax1 = -1e30f;
#pragma unroll
        for (int nf = 0; nf < 8; nf++) {
            rmax0 = fmaxf(rmax0, fmaxf(s[nf][0], s[nf][1]));
            rmax1 = fmaxf(rmax1, fmaxf(s[nf][2], s[nf][3]));
        }
        rmax0 = fmaxf(rmax0, __shfl_xor_sync(0xffffffffu, rmax0, 1));
        rmax0 = fmaxf(rmax0, __shfl_xor_sync(0xffffffffu, rmax0, 2));
        rmax1 = fmaxf(rmax1, __shfl_xor_sync(0xffffffffu, rmax1, 1));
        rmax1 = fmaxf(rmax1, __shfl_xor_sync(0xffffffffu, rmax1, 2));

        float mn0 = fmaxf(m0, rmax0), mn1 = fmaxf(m1, rmax1);
        float corr0 = __expf(m0 - mn0), corr1 = __expf(m1 - mn1);
        m0 = mn0; m1 = mn1;

        float rs0 = 0.f, rs1 = 0.f;
#pragma unroll
        for (int nf = 0; nf < 8; nf++) {
            s[nf][0] = __expf(s[nf][0] - mn0); rs0 += s[nf][0];
            s[nf][1] = __expf(s[nf][1] - mn0); rs0 += s[nf][1];
            s[nf][2] = __expf(s[nf][2] - mn1); rs1 += s[nf][2];
            s[nf][3] = __expf(s[nf][3] - mn1); rs1 += s[nf][3];
        }
        rs0 += __shfl_xor_sync(0xffffffffu, rs0, 1);
        rs0 += __shfl_xor_sync(0xffffffffu, rs0, 2);
        rs1 += __shfl_xor_sync(0xffffffffu, rs1, 1);
        rs1 += __shfl_xor_sync(0xffffffffu, rs1, 2);
        l0 = l0 * corr0 + rs0;
        l1 = l1 * corr1 + rs1;

#pragma unroll
        for (int nf = 0; nf < 8; nf++) {
            int col = nf * 8 + 2 * tig;
            *(float2*)&Ps[(qr0 + g    ) * LDS_P + col] =
                make_float2(to_tf32(s[nf][0]), to_tf32(s[nf][1]));
            *(float2*)&Ps[(qr0 + g + 8) * LDS_P + col] =
                make_float2(to_tf32(s[nf][2]), to_tf32(s[nf][3]));
        }
        __syncwarp();

#pragma unroll
        for (int df = 0; df < 8; df++) {
            o[df][0] *= corr0; o[df][1] *= corr0;
            o[df][2] *= corr1; o[df][3] *= corr1;
        }
#pragma unroll
        for (int ks = 0; ks < 8; ks++) {
            int k0 = ks * 8;
            uint32_t pa0 = __float_as_uint(Ps[(qr0 + g    ) * LDS_P + k0 + tig    ]);
            uint32_t pa1 = __float_as_uint(Ps[(qr0 + g + 8) * LDS_P + k0 + tig    ]);
            uint32_t pa2 = __float_as_uint(Ps[(qr0 + g    ) * LDS_P + k0 + tig + 4]);
            uint32_t pa3 = __float_as_uint(Ps[(qr0 + g + 8) * LDS_P + k0 + tig + 4]);
#pragma unroll
            for (int df = 0; df < 8; df++) {
                uint32_t vb0 = __float_as_uint(Vs[cV + (k0 + tig    ) * LDS_V + df * 8 + g]);
                uint32_t vb1 = __float_as_uint(Vs[cV + (k0 + tig + 4) * LDS_V + df * 8 + g]);
                mma_tf32_16x8x8(o[df][0], o[df][1], o[df][2], o[df][3],
                                pa0, pa1, pa2, pa3, vb0, vb1);
            }
        }
    }

    float inv0 = 1.f / l0, inv1 = 1.f / l1;
    float* obase = ctx + ((size_t)b * TQ + t0) * D_MODEL + h * HDIM;
#pragma unroll
    for (int df = 0; df < 8; df++) {
        int col = df * 8 + 2 * tig;
        *(float2*)&obase[(size_t)(qr0 + g    ) * D_MODEL + col] =
            make_float2(to_tf32(o[df][0] * inv0), to_tf32(o[df][1] * inv0));
        *(float2*)&obase[(size_t)(qr0 + g + 8) * D_MODEL + col] =
            make_float2(to_tf32(o[df][2] * inv1), to_tf32(o[df][3] * inv1));
    }
}

// ---------------------------------------------------------------------------
extern "C" void kernel_launch(void* const* d_in, const int* in_sizes, int n_in,
                              void* d_out, int out_size)
{
    const float* query = (const float*)d_in[0];
    const float* kv    = (const float*)d_in[1];
    const unsigned char* mask = (const unsigned char*)d_in[2];
    const float* Wq = (const float*)d_in[3];
    const float* bq = (const float*)d_in[4];
    const float* Wk = (const float*)d_in[5];
    const float* bk = (const float*)d_in[6];
    const float* Wv = (const float*)d_in[7];
    const float* bv = (const float*)d_in[8];
    const float* Wo = (const float*)d_in[9];
    const float* bo = (const float*)d_in[10];
    float* out = (float*)d_out;

    static float *qb = nullptr, *kb = nullptr, *vbuf = nullptr, *cb = nullptr;
    static float *qin = nullptr, *kvin = nullptr;
    static float *wq = nullptr, *wk = nullptr, *wv = nullptr, *wo = nullptr;
    static const int SMEM_GEMM = 4 * 128 * 36 * 4;                        // 73728
    static const int SMEM_ATTN =
        (BQ * LDS_P + STAGES * BKV * LDS_K + STAGES * BKV * LDS_V) * 4
        + STAGES * BKV;                                                    // 106624
    if (!qb) {
        cudaGetSymbolAddress((void**)&qb,   g_q);
        cudaGetSymbolAddress((void**)&kb,   g_k);
        cudaGetSymbolAddress((void**)&vbuf, g_v);
        cudaGetSymbolAddress((void**)&cb,   g_ctx);
        cudaGetSymbolAddress((void**)&qin,  g_qin);
        cudaGetSymbolAddress((void**)&kvin, g_kvin);
        cudaGetSymbolAddress((void**)&wq,   g_wq);
        cudaGetSymbolAddress((void**)&wk,   g_wk);
        cudaGetSymbolAddress((void**)&wv,   g_wv);
        cudaGetSymbolAddress((void**)&wo,   g_wo);
        cudaFuncSetAttribute(gemm_qkv_fused,
                             cudaFuncAttributeMaxDynamicSharedMemorySize, SMEM_GEMM);
        cudaFuncSetAttribute(gemm_o_proj,
                             cudaFuncAttributeMaxDynamicSharedMemorySize, SMEM_GEMM);
        cudaFuncSetAttribute(attn_tc_kernel,
                             cudaFuncAttributeMaxDynamicSharedMemorySize, SMEM_ATTN);
    }

    dim3 blk(256);
    // One fused cvt launch over all inputs (25165824 floats / 4 / 256)
    cvt_all_kernel<<<24576, blk>>>(query, qin, kv, kvin,
                                   Wq, wq, Wk, wk, Wv, wv, Wo, wo);

    // Fused Q/K/V projections: 8 x (64+96+96) CTAs in one launch
    gemm_qkv_fused<<<dim3(8, 256), blk, SMEM_GEMM>>>(
        qin, kvin, wq, bq, qb, wk, bk, kb, wv, bv, vbuf);

    attn_tc_kernel<<<dim3(TQ / BQ, B_ * NH), blk, SMEM_ATTN>>>(qb, kb, vbuf, mask, cb);

    gemm_o_proj<<<dim3(8, 64), blk, SMEM_GEMM>>>(cb, wo, bo, out);
}

// round 13
// speedup vs baseline: 3.9820x; 1.0060x over previous
#include <cuda_runtime.h>
#include <cstdint>

#define D_MODEL 1024
#define NH      16
#define HDIM    64
#define B_      8
#define TQ      1024
#define NKV     1536
#define SCALE   0.125f   // HD^-0.5 (exact power of two)

// attention tiles
#define BQ     128
#define BKV    64
#define LDS_P  68
#define LDS_K  68
#define LDS_V  72
#define STAGES 2
// gemm ring
#define GSTAGES 3

// Scratch (allocation-free rule: __device__ globals)
__device__ float g_q[B_ * TQ * D_MODEL];      // tf32(q_proj*SCALE)
__device__ float g_k[B_ * NKV * D_MODEL];     // tf32(k_proj)
__device__ float g_v[B_ * NKV * D_MODEL];     // tf32(v_proj)
__device__ float g_ctx[B_ * TQ * D_MODEL];    // tf32(attention out)
__device__ float g_qin[B_ * TQ * D_MODEL];    // tf32(query)
__device__ float g_kvin[B_ * NKV * D_MODEL];  // tf32(key_value)
__device__ float g_wq[D_MODEL * D_MODEL];     // tf32 weights
__device__ float g_wk[D_MODEL * D_MODEL];
__device__ float g_wv[D_MODEL * D_MODEL];
__device__ float g_wo[D_MODEL * D_MODEL];

// ---------------------------------------------------------------------------
__device__ __forceinline__ float to_tf32(float x) {
    uint32_t y;
    asm("cvt.rna.tf32.f32 %0, %1;" : "=r"(y) : "f"(x));
    return __uint_as_float(y);
}

__device__ __forceinline__ void mma_tf32_16x8x8(
    float& c0, float& c1, float& c2, float& c3,
    uint32_t a0, uint32_t a1, uint32_t a2, uint32_t a3,
    uint32_t b0, uint32_t b1)
{
    asm volatile(
        "mma.sync.aligned.m16n8k8.row.col.f32.tf32.tf32.f32 "
        "{%0,%1,%2,%3}, {%4,%5,%6,%7}, {%8,%9}, {%0,%1,%2,%3};\n"
        : "+f"(c0), "+f"(c1), "+f"(c2), "+f"(c3)
        : "r"(a0), "r"(a1), "r"(a2), "r"(a3), "r"(b0), "r"(b1));
}

__device__ __forceinline__ uint32_t smem_u32(const void* p) {
    uint32_t a;
    asm("{ .reg .u64 t; cvta.to.shared.u64 t, %1; cvt.u32.u64 %0, t; }"
        : "=r"(a) : "l"(p));
    return a;
}

#define CP_ASYNC16(dst, src) \
    asm volatile("cp.async.cg.shared.global [%0], [%1], 16;" \
                 :: "r"(dst), "l"(src) : "memory")
#define CP_COMMIT() asm volatile("cp.async.commit_group;" ::: "memory")
#define CP_WAIT(n)  asm volatile("cp.async.wait_group %0;" :: "n"(n) : "memory")

// ---------------------------------------------------------------------------
// Fused elementwise tf32 rounding over all 6 input arrays (one launch).
// ---------------------------------------------------------------------------
__global__ __launch_bounds__(256) void cvt_all_kernel(
    const float* __restrict__ query, float* __restrict__ qin,
    const float* __restrict__ kv,    float* __restrict__ kvin,
    const float* __restrict__ Wq, float* __restrict__ wq,
    const float* __restrict__ Wk, float* __restrict__ wk,
    const float* __restrict__ Wv, float* __restrict__ wv,
    const float* __restrict__ Wo, float* __restrict__ wo)
{
    const int NQ = B_ * TQ * D_MODEL;
    const int NKVE = B_ * NKV * D_MODEL;
    const int NW = D_MODEL * D_MODEL;
    int i = (blockIdx.x * 256 + threadIdx.x) * 4;
    const float* src; float* dst; int off;
    if (i < NQ)                       { src = query; dst = qin;  off = i; }
    else if (i < NQ + NKVE)           { src = kv;    dst = kvin; off = i - NQ; }
    else if (i < NQ + NKVE + NW)      { src = Wq; dst = wq; off = i - NQ - NKVE; }
    else if (i < NQ + NKVE + 2 * NW)  { src = Wk; dst = wk; off = i - NQ - NKVE - NW; }
    else if (i < NQ + NKVE + 3 * NW)  { src = Wv; dst = wv; off = i - NQ - NKVE - 2 * NW; }
    else                              { src = Wo; dst = wo; off = i - NQ - NKVE - 3 * NW; }
    float4 v = *(const float4*)(src + off);
    v.x = to_tf32(v.x); v.y = to_tf32(v.y);
    v.z = to_tf32(v.z); v.w = to_tf32(v.w);
    *(float4*)(dst + off) = v;
}

// ---------------------------------------------------------------------------
// GEMM body: C tile [bm:bm+128, bn:bn+128] = A @ W^T + bias (N=K=1024).
// Inputs pre-rounded tf32; cp.async 3-stage ring (CP_WAIT(1): one group in
// flight while computing). Numerics identical to R12.
// ---------------------------------------------------------------------------
__device__ __forceinline__ void gemm_body(
    float* gsm,
    const float* __restrict__ A, const float* __restrict__ W,
    const float* __restrict__ bias, float* __restrict__ C,
    int bm, int bn, float oscale, int oround)
{
    const int N = D_MODEL, K = D_MODEL;
    float* As = gsm;                          // [3][128][36]
    float* Bs = gsm + GSTAGES * 128 * 36;     // [3][128][36]
    const uint32_t as_u32 = smem_u32(As);
    const uint32_t bs_u32 = smem_u32(Bs);

    const int tid  = threadIdx.x;
    const int wid  = tid >> 5;
    const int lane = tid & 31;
    const int g    = lane >> 2;
    const int tig  = lane & 3;
    const int warp_m = (wid >> 2) * 64;
    const int warp_n = (wid & 3) * 32;

    const int crow = tid >> 3;
    const int ccol = (tid & 7) * 4;

    const float* aptr = A + (size_t)(bm + crow) * K + ccol;
    const float* bptr = W + (size_t)(bn + crow) * K + ccol;

    float acc[4][4][4];
#pragma unroll
    for (int mf = 0; mf < 4; mf++)
#pragma unroll
        for (int nf = 0; nf < 4; nf++)
#pragma unroll
            for (int r = 0; r < 4; r++) acc[mf][nf][r] = 0.f;

    // prologue: tiles 0,1 -> slots 0,1 (two groups)
#pragma unroll
    for (int p = 0; p < 2; p++) {
        const float* ap = aptr + (size_t)p * 32;
        const float* bp = bptr + (size_t)p * 32;
        const int so = p * 128 * 36;
#pragma unroll
        for (int u = 0; u < 4; u++) {
            int r = crow + u * 32;
            CP_ASYNC16(as_u32 + (uint32_t)(so + r * 36 + ccol) * 4,
                       ap + (size_t)u * 32 * K);
            CP_ASYNC16(bs_u32 + (uint32_t)(so + r * 36 + ccol) * 4,
                       bp + (size_t)u * 32 * K);
        }
        CP_COMMIT();
    }

    const int kTiles = K >> 5;
    int cur = 0, nslot = 2;        // slot of tile kt; slot for tile kt+2
    for (int kt = 0; kt < kTiles; kt++) {
        CP_WAIT(1);                // tile kt arrived (kt+1 may be in flight)
        __syncthreads();           // all threads done computing tile kt-1
        if (kt + 2 < kTiles) {
            const float* ap = aptr + (size_t)(kt + 2) * 32;
            const float* bp = bptr + (size_t)(kt + 2) * 32;
            const int so = nslot * 128 * 36;
#pragma unroll
            for (int u = 0; u < 4; u++) {
                int r = crow + u * 32;
                CP_ASYNC16(as_u32 + (uint32_t)(so + r * 36 + ccol) * 4,
                           ap + (size_t)u * 32 * K);
                CP_ASYNC16(bs_u32 + (uint32_t)(so + r * 36 + ccol) * 4,
                           bp + (size_t)u * 32 * K);
            }
        }
        CP_COMMIT();

        const int co = cur * 128 * 36;
#pragma unroll
        for (int ks = 0; ks < 4; ks++) {
            const int k0 = ks * 8;
            uint32_t af[4][4];
#pragma unroll
            for (int mf = 0; mf < 4; mf++) {
                int row = warp_m + mf * 16;
                af[mf][0] = __float_as_uint(As[co + (row + g    ) * 36 + k0 + tig    ]);
                af[mf][1] = __float_as_uint(As[co + (row + g + 8) * 36 + k0 + tig    ]);
                af[mf][2] = __float_as_uint(As[co + (row + g    ) * 36 + k0 + tig + 4]);
                af[mf][3] = __float_as_uint(As[co + (row + g + 8) * 36 + k0 + tig + 4]);
            }
            uint32_t bf[4][2];
#pragma unroll
            for (int nf = 0; nf < 4; nf++) {
                int col = warp_n + nf * 8;
                bf[nf][0] = __float_as_uint(Bs[co + (col + g) * 36 + k0 + tig    ]);
                bf[nf][1] = __float_as_uint(Bs[co + (col + g) * 36 + k0 + tig + 4]);
            }
#pragma unroll
            for (int mf = 0; mf < 4; mf++)
#pragma unroll
                for (int nf = 0; nf < 4; nf++)
                    mma_tf32_16x8x8(acc[mf][nf][0], acc[mf][nf][1],
                                    acc[mf][nf][2], acc[mf][nf][3],
                                    af[mf][0], af[mf][1], af[mf][2], af[mf][3],
                                    bf[nf][0], bf[nf][1]);
        }
        cur   = (cur + 1 == GSTAGES) ? 0 : cur + 1;
        nslot = (nslot + 1 == GSTAGES) ? 0 : nslot + 1;
    }

#pragma unroll
    for (int mf = 0; mf < 4; mf++) {
        int row0 = bm + warp_m + mf * 16 + g;
#pragma unroll
        for (int nf = 0; nf < 4; nf++) {
            int col = bn + warp_n + nf * 8 + 2 * tig;
            float bv0 = bias[col], bv1 = bias[col + 1];
            float v00 = (acc[mf][nf][0] + bv0) * oscale;
            float v01 = (acc[mf][nf][1] + bv1) * oscale;
            float v10 = (acc[mf][nf][2] + bv0) * oscale;
            float v11 = (acc[mf][nf][3] + bv1) * oscale;
            if (oround) {
                v00 = to_tf32(v00); v01 = to_tf32(v01);
                v10 = to_tf32(v10); v11 = to_tf32(v11);
            }
            *(float2*)&C[(size_t)row0 * N + col]       = make_float2(v00, v01);
            *(float2*)&C[(size_t)(row0 + 8) * N + col] = make_float2(v10, v11);
        }
    }
}

// ---------------------------------------------------------------------------
// Fused Q/K/V projection launch: grid (8, 64+96+96). Job from blockIdx.y.
// ---------------------------------------------------------------------------
__global__ __launch_bounds__(256, 2) void gemm_qkv_fused(
    const float* __restrict__ qin, const float* __restrict__ kvin,
    const float* __restrict__ wq, const float* __restrict__ bq, float* __restrict__ qb,
    const float* __restrict__ wk, const float* __restrict__ bk, float* __restrict__ kb,
    const float* __restrict__ wv, const float* __restrict__ bv, float* __restrict__ vb)
{
    extern __shared__ float gsm[];
    const int y = blockIdx.y;
    const int bn = blockIdx.x * 128;
    if (y < 64) {
        gemm_body(gsm, qin, wq, bq, qb, y * 128, bn, SCALE, 1);
    } else if (y < 160) {
        gemm_body(gsm, kvin, wk, bk, kb, (y - 64) * 128, bn, 1.0f, 1);
    } else {
        gemm_body(gsm, kvin, wv, bv, vb, (y - 160) * 128, bn, 1.0f, 1);
    }
}

// O-projection (fp32 epilogue, ctx already tf32)
__global__ __launch_bounds__(256, 2) void gemm_o_proj(
    const float* __restrict__ cb, const float* __restrict__ wo,
    const float* __restrict__ bo, float* __restrict__ out)
{
    extern __shared__ float gsm[];
    gemm_body(gsm, cb, wo, bo, out, blockIdx.y * 128, blockIdx.x * 128, 1.0f, 0);
}

// ---------------------------------------------------------------------------
__device__ __forceinline__ void stage_kv(
    uint32_t ks_u32, uint32_t vs_u32, uint32_t ms_u32, int slot,
    const float* kp, const float* vp, const unsigned char* mp,
    int sr, int sc, int tid)
{
#pragma unroll
    for (int u = 0; u < 4; u++) {
        int r = sr + u * 16;
        CP_ASYNC16(ks_u32 + (uint32_t)(slot * BKV * LDS_K + r * LDS_K + sc) * 4,
                   kp + (size_t)r * D_MODEL + sc);
        CP_ASYNC16(vs_u32 + (uint32_t)(slot * BKV * LDS_V + r * LDS_V + sc) * 4,
                   vp + (size_t)r * D_MODEL + sc);
    }
    if (tid < 4)
        CP_ASYNC16(ms_u32 + (uint32_t)(slot * BKV + tid * 16), mp + tid * 16);
}

// ---------------------------------------------------------------------------
// Tensor-core flash attention (unchanged from R12): cp.async 2-stage ring,
// 2 CTAs/SM, tf32-rounded epilogue.
// ---------------------------------------------------------------------------
__global__ __launch_bounds__(256, 2) void attn_tc_kernel(
    const float* __restrict__ qb, const float* __restrict__ kb,
    const float* __restrict__ vb, const unsigned char* __restrict__ mask,
    float* __restrict__ ctx)
{
    extern __shared__ float sm[];
    float* Ps = sm;                               // [128][LDS_P]
    float* Ks = Ps + BQ * LDS_P;                  // [2][64][LDS_K]
    float* Vs = Ks + STAGES * BKV * LDS_K;        // [2][64][LDS_V]
    unsigned char* Ms = (unsigned char*)(Vs + STAGES * BKV * LDS_V);  // [2][64]

    const int tid  = threadIdx.x;
    const int wid  = tid >> 5;
    const int lane = tid & 31;
    const int g    = lane >> 2;
    const int tig  = lane & 3;
    const int qr0  = wid * 16;
    const int b = blockIdx.y / NH;
    const int h = blockIdx.y % NH;
    const int t0 = blockIdx.x * BQ;

    const int sr = tid >> 4;
    const int sc = (tid & 15) * 4;

    const uint32_t ps_u32 = smem_u32(Ps);
    const uint32_t ks_u32 = smem_u32(Ks);
    const uint32_t vs_u32 = smem_u32(Vs);
    const uint32_t ms_u32 = smem_u32(Ms);

    const float* qbase = qb + ((size_t)b * TQ + t0) * D_MODEL + h * HDIM;
    const float* kbase = kb + ((size_t)b * NKV) * D_MODEL + h * HDIM;
    const float* vbase = vb + ((size_t)b * NKV) * D_MODEL + h * HDIM;
    const unsigned char* mbase = mask + (size_t)b * NKV;

#pragma unroll
    for (int u = 0; u < 8; u++) {
        int idx = tid + u * 256;
        int r = idx >> 4, c = (idx & 15) * 4;
        CP_ASYNC16(ps_u32 + (uint32_t)(r * LDS_P + c) * 4,
                   qbase + (size_t)r * D_MODEL + c);
    }
    CP_COMMIT();
    stage_kv(ks_u32, vs_u32, ms_u32, 0, kbase, vbase, mbase, sr, sc, tid);
    CP_COMMIT();

    CP_WAIT(1);
    __syncthreads();

    uint32_t qa[8][4];
#pragma unroll
    for (int ks = 0; ks < 8; ks++) {
        int k0 = ks * 8;
        qa[ks][0] = __float_as_uint(Ps[(qr0 + g    ) * LDS_P + k0 + tig    ]);
        qa[ks][1] = __float_as_uint(Ps[(qr0 + g + 8) * LDS_P + k0 + tig    ]);
        qa[ks][2] = __float_as_uint(Ps[(qr0 + g    ) * LDS_P + k0 + tig + 4]);
        qa[ks][3] = __float_as_uint(Ps[(qr0 + g + 8) * LDS_P + k0 + tig + 4]);
    }

    float m0 = -1e30f, m1 = -1e30f, l0 = 0.f, l1 = 0.f;
    float o[8][4];
#pragma unroll
    for (int df = 0; df < 8; df++)
#pragma unroll
        for (int r = 0; r < 4; r++) o[df][r] = 0.f;

    const int nTiles = NKV / BKV;      // 24
    for (int t = 0; t < nTiles; t++) {
        const int slot = t & 1;
        CP_WAIT(0);
        __syncthreads();

        if (t + 1 < nTiles) {
            stage_kv(ks_u32, vs_u32, ms_u32, 1 - slot,
                     kbase + (size_t)(t + 1) * BKV * D_MODEL,
                     vbase + (size_t)(t + 1) * BKV * D_MODEL,
                     mbase + (t + 1) * BKV, sr, sc, tid);
        }
        CP_COMMIT();

        const int cK = slot * BKV * LDS_K;
        const int cV = slot * BKV * LDS_V;
        const int cM = slot * BKV;

        float s[8][4];
#pragma unroll
        for (int nf = 0; nf < 8; nf++) {
            s[nf][0] = 0.f; s[nf][1] = 0.f; s[nf][2] = 0.f; s[nf][3] = 0.f;
#pragma unroll
            for (int ks = 0; ks < 8; ks++) {
                int k0 = ks * 8;
                uint32_t b0 = __float_as_uint(Ks[cK + (nf * 8 + g) * LDS_K + k0 + tig    ]);
                uint32_t b1 = __float_as_uint(Ks[cK + (nf * 8 + g) * LDS_K + k0 + tig + 4]);
                mma_tf32_16x8x8(s[nf][0], s[nf][1], s[nf][2], s[nf][3],
                                qa[ks][0], qa[ks][1], qa[ks][2], qa[ks][3], b0, b1);
            }
        }

#pragma unroll
        for (int nf = 0; nf < 8; nf++) {
            int c0 = cM + nf * 8 + 2 * tig;
            if (Ms[c0])     { s[nf][0] = -1e30f; s[nf][2] = -1e30f; }
            if (Ms[c0 + 1]) { s[nf][1] = -1e30f; s[nf][3] = -1e30f; }
        }

        float rmax0 = -1e30f, rmax1 = -1e30f;
#pragma unroll
        for (int nf = 0; nf < 8; nf++) {
            rmax0 = fmaxf(rmax0, fmaxf(s[nf][0], s[nf][1]));
            rmax1 = fmaxf(rmax1, fmaxf(s[nf][2], s[nf][3]));
        }
        rmax0 = fmaxf(rmax0, __shfl_xor_sync(0xffffffffu, rmax0, 1));
        rmax0 = fmaxf(rmax0, __shfl_xor_sync(0xffffffffu, rmax0, 2));
        rmax1 = fmaxf(rmax1, __shfl_xor_sync(0xffffffffu, rmax1, 1));
        rmax1 = fmaxf(rmax1, __shfl_xor_sync(0xffffffffu, rmax1, 2));

        float mn0 = fmaxf(m0, rmax0), mn1 = fmaxf(m1, rmax1);
        float corr0 = __expf(m0 - mn0), corr1 = __expf(m1 - mn1);
        m0 = mn0; m1 = mn1;

        float rs0 = 0.f, rs1 = 0.f;
#pragma unroll
        for (int nf = 0; nf < 8; nf++) {
            s[nf][0] = __expf(s[nf][0] - mn0); rs0 += s[nf][0];
            s[nf][1] = __expf(s[nf][1] - mn0); rs0 += s[nf][1];
            s[nf][2] = __expf(s[nf][2] - mn1); rs1 += s[nf][2];
            s[nf][3] = __expf(s[nf][3] - mn1); rs1 += s[nf][3];
        }
        rs0 += __shfl_xor_sync(0xffffffffu, rs0, 1);
        rs0 += __shfl_xor_sync(0xffffffffu, rs0, 2);
        rs1 += __shfl_xor_sync(0xffffffffu, rs1, 1);
        rs1 += __shfl_xor_sync(0xffffffffu, rs1, 2);
        l0 = l0 * corr0 + rs0;
        l1 = l1 * corr1 + rs1;

#pragma unroll
        for (int nf = 0; nf < 8; nf++) {
            int col = nf * 8 + 2 * tig;
            *(float2*)&Ps[(qr0 + g    ) * LDS_P + col] =
                make_float2(to_tf32(s[nf][0]), to_tf32(s[nf][1]));
            *(float2*)&Ps[(qr0 + g + 8) * LDS_P + col] =
                make_float2(to_tf32(s[nf][2]), to_tf32(s[nf][3]));
        }
        __syncwarp();

#pragma unroll
        for (int df = 0; df < 8; df++) {
            o[df][0] *= corr0; o[df][1] *= corr0;
            o[df][2] *= corr1; o[df][3] *= corr1;
        }
#pragma unroll
        for (int ks = 0; ks < 8; ks++) {
            int k0 = ks * 8;
            uint32_t pa0 = __float_as_uint(Ps[(qr0 + g    ) * LDS_P + k0 + tig    ]);
            uint32_t pa1 = __float_as_uint(Ps[(qr0 + g + 8) * LDS_P + k0 + tig    ]);
            uint32_t pa2 = __float_as_uint(Ps[(qr0 + g    ) * LDS_P + k0 + tig + 4]);
            uint32_t pa3 = __float_as_uint(Ps[(qr0 + g + 8) * LDS_P + k0 + tig + 4]);
#pragma unroll
            for (int df = 0; df < 8; df++) {
                uint32_t vb0 = __float_as_uint(Vs[cV + (k0 + tig    ) * LDS_V + df * 8 + g]);
                uint32_t vb1 = __float_as_uint(Vs[cV + (k0 + tig + 4) * LDS_V + df * 8 + g]);
                mma_tf32_16x8x8(o[df][0], o[df][1], o[df][2], o[df][3],
                                pa0, pa1, pa2, pa3, vb0, vb1);
            }
        }
    }

    float inv0 = 1.f / l0, inv1 = 1.f / l1;
    float* obase = ctx + ((size_t)b * TQ + t0) * D_MODEL + h * HDIM;
#pragma unroll
    for (int df = 0; df < 8; df++) {
        int col = df * 8 + 2 * tig;
        *(float2*)&obase[(size_t)(qr0 + g    ) * D_MODEL + col] =
            make_float2(to_tf32(o[df][0] * inv0), to_tf32(o[df][1] * inv0));
        *(float2*)&obase[(size_t)(qr0 + g + 8) * D_MODEL + col] =
            make_float2(to_tf32(o[df][2] * inv1), to_tf32(o[df][3] * inv1));
    }
}

// ---------------------------------------------------------------------------
extern "C" void kernel_launch(void* const* d_in, const int* in_sizes, int n_in,
                              void* d_out, int out_size)
{
    const float* query = (const float*)d_in[0];
    const float* kv    = (const float*)d_in[1];
    const unsigned char* mask = (const unsigned char*)d_in[2];
    const float* Wq = (const float*)d_in[3];
    const float* bq = (const float*)d_in[4];
    const float* Wk = (const float*)d_in[5];
    const float* bk = (const float*)d_in[6];
    const float* Wv = (const float*)d_in[7];
    const float* bv = (const float*)d_in[8];
    const float* Wo = (const float*)d_in[9];
    const float* bo = (const float*)d_in[10];
    float* out = (float*)d_out;

    static float *qb = nullptr, *kb = nullptr, *vbuf = nullptr, *cb = nullptr;
    static float *qin = nullptr, *kvin = nullptr;
    static float *wq = nullptr, *wk = nullptr, *wv = nullptr, *wo = nullptr;
    static const int SMEM_GEMM = GSTAGES * 2 * 128 * 36 * 4;              // 110592
    static const int SMEM_ATTN =
        (BQ * LDS_P + STAGES * BKV * LDS_K + STAGES * BKV * LDS_V) * 4
        + STAGES * BKV;                                                    // 106624
    if (!qb) {
        cudaGetSymbolAddress((void**)&qb,   g_q);
        cudaGetSymbolAddress((void**)&kb,   g_k);
        cudaGetSymbolAddress((void**)&vbuf, g_v);
        cudaGetSymbolAddress((void**)&cb,   g_ctx);
        cudaGetSymbolAddress((void**)&qin,  g_qin);
        cudaGetSymbolAddress((void**)&kvin, g_kvin);
        cudaGetSymbolAddress((void**)&wq,   g_wq);
        cudaGetSymbolAddress((void**)&wk,   g_wk);
        cudaGetSymbolAddress((void**)&wv,   g_wv);
        cudaGetSymbolAddress((void**)&wo,   g_wo);
        cudaFuncSetAttribute(gemm_qkv_fused,
                             cudaFuncAttributeMaxDynamicSharedMemorySize, SMEM_GEMM);
        cudaFuncSetAttribute(gemm_o_proj,
                             cudaFuncAttributeMaxDynamicSharedMemorySize, SMEM_GEMM);
        cudaFuncSetAttribute(attn_tc_kernel,
                             cudaFuncAttributeMaxDynamicSharedMemorySize, SMEM_ATTN);
    }

    dim3 blk(256);
    cvt_all_kernel<<<24576, blk>>>(query, qin, kv, kvin,
                                   Wq, wq, Wk, wk, Wv, wv, Wo, wo);

    gemm_qkv_fused<<<dim3(8, 256), blk, SMEM_GEMM>>>(
        qin, kvin, wq, bq, qb, wk, bk, kb, wv, bv, vbuf);

    attn_tc_kernel<<<dim3(TQ / BQ, B_ * NH), blk, SMEM_ATTN>>>(qb, kb, vbuf, mask, cb);

    gemm_o_proj<<<dim3(8, 64), blk, SMEM_GEMM>>>(cb, wo, bo, out);
}